// round 1
// baseline (speedup 1.0000x reference)
#include <cuda_runtime.h>
#include <cuda_bf16.h>

#define N_NODES 50000
#define E_EDGES 800000
#define IN_SZ   256
#define HID     128
#define OUT_SZ  40
#define NUM_STEPS 16
#define LAM   1.0f
#define ALPHA 0.5f

// ---------------- scratch (static device globals; no allocation) ----------------
__device__ float g_H1[N_NODES * HID];   // relu(X@W1+b1)
__device__ float g_Y0[N_NODES * HID];   // MLP output / fixed point anchor
__device__ float g_Ya[N_NODES * HID];   // ping
__device__ float g_Yb[N_NODES * HID];   // pong
__device__ int   g_deg[N_NODES];
__device__ int   g_rowptr[N_NODES + 1];
__device__ int   g_fill[N_NODES];
__device__ int   g_csrcol[E_EDGES];
__device__ float g_invd[N_NODES];

// ---------------- CSR build ----------------
__global__ void zero_deg_kernel() {
    int i = blockIdx.x * blockDim.x + threadIdx.x;
    if (i < N_NODES) g_deg[i] = 0;
}

__global__ void count_edges_kernel(const int* __restrict__ row) {
    for (int e = blockIdx.x * blockDim.x + threadIdx.x; e < E_EDGES;
         e += gridDim.x * blockDim.x) {
        atomicAdd(&g_deg[row[e]], 1);
    }
}

// single-block exclusive scan of g_deg -> g_rowptr / g_fill, plus inv_d
__global__ void scan_kernel() {
    __shared__ int sh[1024];
    __shared__ int carry_s;
    int tid = threadIdx.x;
    if (tid == 0) carry_s = 0;
    __syncthreads();

    for (int base = 0; base < N_NODES; base += 1024) {
        int i = base + tid;
        int v = (i < N_NODES) ? g_deg[i] : 0;
        sh[tid] = v;
        __syncthreads();
        #pragma unroll
        for (int off = 1; off < 1024; off <<= 1) {
            int t = (tid >= off) ? sh[tid - off] : 0;
            __syncthreads();
            sh[tid] += t;
            __syncthreads();
        }
        int excl = carry_s + sh[tid] - v;
        if (i < N_NODES) {
            g_rowptr[i] = excl;
            g_fill[i]   = excl;
            g_invd[i]   = 1.0f / (LAM * (float)v + 1.0f);
        }
        __syncthreads();
        if (tid == 0) carry_s += sh[1023];
        __syncthreads();
    }
    if (tid == 0) g_rowptr[N_NODES] = E_EDGES;
}

__global__ void scatter_edges_kernel(const int* __restrict__ row,
                                     const int* __restrict__ col) {
    for (int e = blockIdx.x * blockDim.x + threadIdx.x; e < E_EDGES;
         e += gridDim.x * blockDim.x) {
        int r = row[e];
        int p = atomicAdd(&g_fill[r], 1);
        g_csrcol[p] = col[e];
    }
}

// ---------------- fused SpMM + TWIRLS update ----------------
// One warp per row. H=128 floats = 32 float4; each lane owns one float4.
// Yout[i] = (1-a)*Yin[i] + a*inv_d[i]*(LAM * sum_{j in N(i)} Yin[j] + Y0[i])
__global__ void spmm_step_kernel(const float4* __restrict__ Yin,
                                 float4* __restrict__ Yout) {
    int w    = (blockIdx.x * blockDim.x + threadIdx.x) >> 5;
    int lane = threadIdx.x & 31;
    if (w >= N_NODES) return;

    int s = g_rowptr[w];
    int e = g_rowptr[w + 1];

    float4 acc = make_float4(0.f, 0.f, 0.f, 0.f);
    for (int t = s; t < e; ++t) {
        int j = g_csrcol[t];
        float4 v = Yin[(size_t)j * 32 + lane];
        acc.x += v.x; acc.y += v.y; acc.z += v.z; acc.w += v.w;
    }

    const float4* Y0v = reinterpret_cast<const float4*>(g_Y0);
    float4 y  = Yin[(size_t)w * 32 + lane];
    float4 y0 = Y0v[(size_t)w * 32 + lane];
    float aid = ALPHA * g_invd[w];

    float4 o;
    o.x = (1.0f - ALPHA) * y.x + aid * (LAM * acc.x + y0.x);
    o.y = (1.0f - ALPHA) * y.y + aid * (LAM * acc.y + y0.y);
    o.z = (1.0f - ALPHA) * y.z + aid * (LAM * acc.z + y0.z);
    o.w = (1.0f - ALPHA) * y.w + aid * (LAM * acc.w + y0.w);
    Yout[(size_t)w * 32 + lane] = o;
}

// ---------------- register-tiled SGEMM (C = [relu](A@W + bias)) ----------------
// A: [M,K] row-major, W: [K,Nc] row-major, C: [M,Nc].
// BM=64, BN=64, BK=16, 256 threads, 4x4 micro-tile per thread.
template <bool RELU>
__global__ void sgemm_kernel(const float* __restrict__ A,
                             const float* __restrict__ W,
                             const float* __restrict__ bias,
                             float* __restrict__ C,
                             int M, int K, int Nc) {
    const int BM = 64, BN = 64, BK = 16;
    __shared__ float As[BK][BM + 4];  // +4 keeps 16B alignment, reduces conflicts
    __shared__ float Ws[BK][BN];

    int tid = threadIdx.x;
    int tx = tid & 15;   // N direction
    int ty = tid >> 4;   // M direction
    int bm = blockIdx.x * BM;
    int bn = blockIdx.y * BN;

    float c[4][4] = {};

    for (int k0 = 0; k0 < K; k0 += BK) {
        // load A tile (BM x BK), transposed into As
        #pragma unroll
        for (int l = 0; l < 4; ++l) {
            int idx = tid + l * 256;
            int ar = idx >> 4;        // 0..63
            int ac = idx & 15;        // 0..15
            int gr = bm + ar;
            As[ac][ar] = (gr < M) ? A[(size_t)gr * K + k0 + ac] : 0.f;
        }
        // load W tile (BK x BN)
        #pragma unroll
        for (int l = 0; l < 4; ++l) {
            int idx = tid + l * 256;
            int wr = idx >> 6;        // 0..15
            int wc = idx & 63;        // 0..63
            int gc = bn + wc;
            Ws[wr][wc] = (gc < Nc) ? W[(size_t)(k0 + wr) * Nc + gc] : 0.f;
        }
        __syncthreads();

        #pragma unroll
        for (int k = 0; k < BK; ++k) {
            float4 a4 = *reinterpret_cast<const float4*>(&As[k][ty * 4]);
            float4 b4 = *reinterpret_cast<const float4*>(&Ws[k][tx * 4]);
            float ra[4] = {a4.x, a4.y, a4.z, a4.w};
            float rb[4] = {b4.x, b4.y, b4.z, b4.w};
            #pragma unroll
            for (int i = 0; i < 4; ++i)
                #pragma unroll
                for (int j = 0; j < 4; ++j)
                    c[i][j] += ra[i] * rb[j];
        }
        __syncthreads();
    }

    #pragma unroll
    for (int i = 0; i < 4; ++i) {
        int gr = bm + ty * 4 + i;
        if (gr >= M) continue;
        #pragma unroll
        for (int j = 0; j < 4; ++j) {
            int gc = bn + tx * 4 + j;
            if (gc < Nc) {
                float v = c[i][j] + bias[gc];
                if (RELU) v = fmaxf(v, 0.f);
                C[(size_t)gr * Nc + gc] = v;
            }
        }
    }
}

// ---------------- launch ----------------
extern "C" void kernel_launch(void* const* d_in, const int* in_sizes, int n_in,
                              void* d_out, int out_size) {
    const float* X    = (const float*)d_in[0];
    const int*   row  = (const int*)d_in[1];
    const int*   col  = (const int*)d_in[2];
    const float* W1   = (const float*)d_in[3];
    const float* b1   = (const float*)d_in[4];
    const float* W2   = (const float*)d_in[5];
    const float* b2   = (const float*)d_in[6];
    const float* Wout = (const float*)d_in[7];
    const float* bout = (const float*)d_in[8];
    float*       out  = (float*)d_out;

    float *pH1, *pY0, *pYa, *pYb;
    cudaGetSymbolAddress((void**)&pH1, g_H1);
    cudaGetSymbolAddress((void**)&pY0, g_Y0);
    cudaGetSymbolAddress((void**)&pYa, g_Ya);
    cudaGetSymbolAddress((void**)&pYb, g_Yb);

    // CSR build
    zero_deg_kernel<<<(N_NODES + 255) / 256, 256>>>();
    count_edges_kernel<<<1024, 256>>>(row);
    scan_kernel<<<1, 1024>>>();
    scatter_edges_kernel<<<1024, 256>>>(row, col);

    // MLP: H1 = relu(X@W1+b1); Y0 = H1@W2+b2
    dim3 g1((N_NODES + 63) / 64, (HID + 63) / 64);
    sgemm_kernel<true><<<g1, 256>>>(X, W1, b1, pH1, N_NODES, IN_SZ, HID);
    sgemm_kernel<false><<<g1, 256>>>(pH1, W2, b2, pY0, N_NODES, HID, HID);

    // 16 propagation steps, ping-pong
    const int spmm_blocks = (N_NODES * 32 + 255) / 256;  // warp per row
    const float* yin = pY0;
    float* yout = pYa;
    for (int k = 0; k < NUM_STEPS; ++k) {
        yout = (k & 1) ? pYb : pYa;
        spmm_step_kernel<<<spmm_blocks, 256>>>(
            reinterpret_cast<const float4*>(yin),
            reinterpret_cast<float4*>(yout));
        yin = yout;
    }

    // output projection
    dim3 g3((N_NODES + 63) / 64, (OUT_SZ + 63) / 64);
    sgemm_kernel<false><<<g3, 256>>>(yin, Wout, bout, out, N_NODES, HID, OUT_SZ);
}

// round 3
// speedup vs baseline: 1.0248x; 1.0248x over previous
#include <cuda_runtime.h>
#include <cuda_fp16.h>
#include <cuda_bf16.h>
#include <cstdint>

#define N_NODES 50000
#define E_EDGES 800000
#define IN_SZ   256
#define HID     128
#define OUT_SZ  40
#define NUM_STEPS 16
#define LAM   1.0f
#define ALPHA 0.5f

// ---------------- scratch (static device globals; no allocation) ----------------
__device__ float g_H1[N_NODES * HID];       // relu(X@W1+b1)
__device__ float g_Y0[N_NODES * HID];       // MLP output / anchor (also initial state)
__device__ float g_Ya[N_NODES * HID];       // fp32 state ping
__device__ float g_Yb[N_NODES * HID];       // fp32 state pong
__device__ __half g_Ha[N_NODES * HID];      // fp16 gather copy ping
__device__ __half g_Hb[N_NODES * HID];      // fp16 gather copy pong
__device__ int   g_deg[N_NODES];
__device__ int   g_rowptr[N_NODES + 1];
__device__ int   g_fill[N_NODES];
__device__ int   g_csrcol[E_EDGES];
__device__ float g_invd[N_NODES];

// ---------------- CSR build ----------------
__global__ void zero_deg_kernel() {
    int i = blockIdx.x * blockDim.x + threadIdx.x;
    if (i < N_NODES) g_deg[i] = 0;
}

__global__ void count_edges_kernel(const int* __restrict__ row) {
    for (int e = blockIdx.x * blockDim.x + threadIdx.x; e < E_EDGES;
         e += gridDim.x * blockDim.x) {
        atomicAdd(&g_deg[row[e]], 1);
    }
}

// single-block exclusive scan of g_deg -> g_rowptr / g_fill, plus inv_d
// warp-shuffle scan: 3 syncthreads per 1024-chunk instead of 20.
__global__ void scan_kernel() {
    __shared__ int wsum[32];
    __shared__ int carry_s;
    int tid = threadIdx.x;
    int lane = tid & 31;
    int wid = tid >> 5;
    if (tid == 0) carry_s = 0;
    __syncthreads();

    for (int base = 0; base < N_NODES; base += 1024) {
        int i = base + tid;
        int v = (i < N_NODES) ? g_deg[i] : 0;
        int x = v;
        #pragma unroll
        for (int off = 1; off < 32; off <<= 1) {
            int t = __shfl_up_sync(0xffffffffu, x, off);
            if (lane >= off) x += t;
        }
        if (lane == 31) wsum[wid] = x;
        __syncthreads();
        if (wid == 0) {
            int s = wsum[lane];
            #pragma unroll
            for (int off = 1; off < 32; off <<= 1) {
                int t = __shfl_up_sync(0xffffffffu, s, off);
                if (lane >= off) s += t;
            }
            wsum[lane] = s;  // inclusive scan of warp sums
        }
        __syncthreads();
        int woff = (wid == 0) ? 0 : wsum[wid - 1];
        int excl = carry_s + woff + x - v;
        if (i < N_NODES) {
            g_rowptr[i] = excl;
            g_fill[i]   = excl;
            g_invd[i]   = 1.0f / (LAM * (float)v + 1.0f);
        }
        __syncthreads();
        if (tid == 0) carry_s += wsum[31];
        __syncthreads();
    }
    if (tid == 0) g_rowptr[N_NODES] = E_EDGES;
}

__global__ void scatter_edges_kernel(const int* __restrict__ row,
                                     const int* __restrict__ col) {
    for (int e = blockIdx.x * blockDim.x + threadIdx.x; e < E_EDGES;
         e += gridDim.x * blockDim.x) {
        int r = row[e];
        int p = atomicAdd(&g_fill[r], 1);
        g_csrcol[p] = col[e];
    }
}

// ---------------- fused SpMM + TWIRLS update ----------------
// One warp per row, lane owns 4 of the 128 features.
// Gather reads the fp16 copy (256B/row); state read/write stays fp32.
// Yout[i] = (1-a)*Yin[i] + a*inv_d[i]*(LAM * sum_{j in N(i)} Yh[j] + Y0[i])
__global__ void spmm_step_kernel(const float4* __restrict__ Yin,
                                 const uint2*  __restrict__ Hin,
                                 float4*       __restrict__ Yout,
                                 uint2*        __restrict__ Hout) {
    int w    = (blockIdx.x * blockDim.x + threadIdx.x) >> 5;
    int lane = threadIdx.x & 31;
    if (w >= N_NODES) return;

    int s = g_rowptr[w];
    int e = g_rowptr[w + 1];

    float4 acc = make_float4(0.f, 0.f, 0.f, 0.f);
    int base = s;
    while (base < e) {
        int chunk = min(32, e - base);
        int cj = (lane < chunk) ? g_csrcol[base + lane] : 0;
        int k = 0;
        for (; k + 2 <= chunk; k += 2) {
            int j0 = __shfl_sync(0xffffffffu, cj, k);
            int j1 = __shfl_sync(0xffffffffu, cj, k + 1);
            uint2 u0 = Hin[(size_t)j0 * 32 + lane];
            uint2 u1 = Hin[(size_t)j1 * 32 + lane];
            float2 a0 = __half22float2(*reinterpret_cast<__half2*>(&u0.x));
            float2 a1 = __half22float2(*reinterpret_cast<__half2*>(&u0.y));
            float2 b0 = __half22float2(*reinterpret_cast<__half2*>(&u1.x));
            float2 b1 = __half22float2(*reinterpret_cast<__half2*>(&u1.y));
            acc.x += a0.x + b0.x;
            acc.y += a0.y + b0.y;
            acc.z += a1.x + b1.x;
            acc.w += a1.y + b1.y;
        }
        if (k < chunk) {
            int j0 = __shfl_sync(0xffffffffu, cj, k);
            uint2 u0 = Hin[(size_t)j0 * 32 + lane];
            float2 a0 = __half22float2(*reinterpret_cast<__half2*>(&u0.x));
            float2 a1 = __half22float2(*reinterpret_cast<__half2*>(&u0.y));
            acc.x += a0.x; acc.y += a0.y; acc.z += a1.x; acc.w += a1.y;
        }
        base += chunk;
    }

    const float4* Y0v = reinterpret_cast<const float4*>(g_Y0);
    float4 y  = Yin[(size_t)w * 32 + lane];
    float4 y0 = Y0v[(size_t)w * 32 + lane];
    float aid = ALPHA * g_invd[w];

    float4 o;
    o.x = (1.0f - ALPHA) * y.x + aid * (LAM * acc.x + y0.x);
    o.y = (1.0f - ALPHA) * y.y + aid * (LAM * acc.y + y0.y);
    o.z = (1.0f - ALPHA) * y.z + aid * (LAM * acc.z + y0.z);
    o.w = (1.0f - ALPHA) * y.w + aid * (LAM * acc.w + y0.w);
    Yout[(size_t)w * 32 + lane] = o;

    __half2 h01 = __float22half2_rn(make_float2(o.x, o.y));
    __half2 h23 = __float22half2_rn(make_float2(o.z, o.w));
    uint2 hu;
    hu.x = *reinterpret_cast<unsigned int*>(&h01);
    hu.y = *reinterpret_cast<unsigned int*>(&h23);
    Hout[(size_t)w * 32 + lane] = hu;
}

// ---------------- register-tiled SGEMM (C = [relu](A@W + bias)) ----------------
// A: [M,K] row-major, W: [K,Nc] row-major, C: [M,Nc].
// BM=128, BN=64, BK=16, 256 threads, 8x4 micro-tile per thread.
// Optional fp16 mirror of C (for the gather copy of Y0).
template <bool RELU, bool HOUT>
__global__ void sgemm_kernel(const float* __restrict__ A,
                             const float* __restrict__ W,
                             const float* __restrict__ bias,
                             float* __restrict__ C,
                             __half* __restrict__ Ch,
                             int M, int K, int Nc) {
    const int BM = 128, BN = 64, BK = 16;
    const int AS = BM + 4;                 // padded row stride (floats)
    __shared__ float As[BK][AS];
    __shared__ float Ws[BK][BN];

    int tid = threadIdx.x;
    int tx = tid & 15;    // N direction: 16 x 4 = 64
    int ty = tid >> 4;    // M direction: 16 x 8 = 128
    int bm = blockIdx.x * BM;
    int bn = blockIdx.y * BN;

    float c[8][4] = {};

    for (int k0 = 0; k0 < K; k0 += BK) {
        // load A tile (BM x BK) as float4, store transposed into As[k][m]
        #pragma unroll
        for (int l = 0; l < 2; ++l) {
            int fid = tid + l * 256;       // 0..511
            int ar = fid >> 2;             // 0..127
            int ac4 = (fid & 3) * 4;       // 0,4,8,12
            int gr = bm + ar;
            float4 v = make_float4(0.f, 0.f, 0.f, 0.f);
            if (gr < M)
                v = *reinterpret_cast<const float4*>(&A[(size_t)gr * K + k0 + ac4]);
            As[ac4 + 0][ar] = v.x;
            As[ac4 + 1][ar] = v.y;
            As[ac4 + 2][ar] = v.z;
            As[ac4 + 3][ar] = v.w;
        }
        // load W tile (BK x BN) as float4 (contiguous store)
        {
            int wr = tid >> 4;             // 0..15
            int wc4 = (tid & 15) * 4;      // 0..60
            int gc = bn + wc4;
            float4 v = make_float4(0.f, 0.f, 0.f, 0.f);
            if (gc + 3 < Nc) {
                v = *reinterpret_cast<const float4*>(&W[(size_t)(k0 + wr) * Nc + gc]);
            } else {
                if (gc + 0 < Nc) v.x = W[(size_t)(k0 + wr) * Nc + gc + 0];
                if (gc + 1 < Nc) v.y = W[(size_t)(k0 + wr) * Nc + gc + 1];
                if (gc + 2 < Nc) v.z = W[(size_t)(k0 + wr) * Nc + gc + 2];
            }
            *reinterpret_cast<float4*>(&Ws[wr][wc4]) = v;
        }
        __syncthreads();

        #pragma unroll
        for (int k = 0; k < BK; ++k) {
            float4 a0 = *reinterpret_cast<const float4*>(&As[k][ty * 8 + 0]);
            float4 a1 = *reinterpret_cast<const float4*>(&As[k][ty * 8 + 4]);
            float4 b4 = *reinterpret_cast<const float4*>(&Ws[k][tx * 4]);
            float ra[8] = {a0.x, a0.y, a0.z, a0.w, a1.x, a1.y, a1.z, a1.w};
            float rb[4] = {b4.x, b4.y, b4.z, b4.w};
            #pragma unroll
            for (int i = 0; i < 8; ++i)
                #pragma unroll
                for (int j = 0; j < 4; ++j)
                    c[i][j] += ra[i] * rb[j];
        }
        __syncthreads();
    }

    #pragma unroll
    for (int i = 0; i < 8; ++i) {
        int gr = bm + ty * 8 + i;
        if (gr >= M) continue;
        #pragma unroll
        for (int j = 0; j < 4; ++j) {
            int gc = bn + tx * 4 + j;
            if (gc < Nc) {
                float v = c[i][j] + bias[gc];
                if (RELU) v = fmaxf(v, 0.f);
                C[(size_t)gr * Nc + gc] = v;
                if (HOUT) Ch[(size_t)gr * Nc + gc] = __float2half_rn(v);
            }
        }
    }
}

// ---------------- launch ----------------
extern "C" void kernel_launch(void* const* d_in, const int* in_sizes, int n_in,
                              void* d_out, int out_size) {
    const float* X    = (const float*)d_in[0];
    const int*   row  = (const int*)d_in[1];
    const int*   col  = (const int*)d_in[2];
    const float* W1   = (const float*)d_in[3];
    const float* b1   = (const float*)d_in[4];
    const float* W2   = (const float*)d_in[5];
    const float* b2   = (const float*)d_in[6];
    const float* Wout = (const float*)d_in[7];
    const float* bout = (const float*)d_in[8];
    float*       out  = (float*)d_out;

    float *pH1, *pY0, *pYa, *pYb;
    __half *pHa, *pHb;
    cudaGetSymbolAddress((void**)&pH1, g_H1);
    cudaGetSymbolAddress((void**)&pY0, g_Y0);
    cudaGetSymbolAddress((void**)&pYa, g_Ya);
    cudaGetSymbolAddress((void**)&pYb, g_Yb);
    cudaGetSymbolAddress((void**)&pHa, g_Ha);
    cudaGetSymbolAddress((void**)&pHb, g_Hb);

    // CSR build
    zero_deg_kernel<<<(N_NODES + 255) / 256, 256>>>();
    count_edges_kernel<<<1024, 256>>>(row);
    scan_kernel<<<1, 1024>>>();
    scatter_edges_kernel<<<1024, 256>>>(row, col);

    // MLP: H1 = relu(X@W1+b1); Y0 = H1@W2+b2 (fp32 + fp16 mirror)
    dim3 g1((N_NODES + 127) / 128, (HID + 63) / 64);
    sgemm_kernel<true, false><<<g1, 256>>>(X, W1, b1, pH1, nullptr,
                                           N_NODES, IN_SZ, HID);
    sgemm_kernel<false, true><<<g1, 256>>>(pH1, W2, b2, pY0, pHa,
                                           N_NODES, HID, HID);

    // 16 propagation steps, ping-pong (fp32 state + fp16 gather copy)
    const int spmm_blocks = (N_NODES * 32 + 255) / 256;  // warp per row
    const float* yin = pY0;
    const __half* hin = pHa;
    for (int k = 0; k < NUM_STEPS; ++k) {
        float*  yout = (k & 1) ? pYb : pYa;
        __half* hout = (k & 1) ? pHa : pHb;  // k=0 writes Hb (Ha holds Y0 copy)
        spmm_step_kernel<<<spmm_blocks, 256>>>(
            reinterpret_cast<const float4*>(yin),
            reinterpret_cast<const uint2*>(hin),
            reinterpret_cast<float4*>(yout),
            reinterpret_cast<uint2*>(hout));
        yin = yout;
        hin = hout;
    }

    // output projection
    dim3 g3((N_NODES + 127) / 128, (OUT_SZ + 63) / 64);
    sgemm_kernel<false, false><<<g3, 256>>>(yin, Wout, bout, out, nullptr,
                                            N_NODES, HID, OUT_SZ);
}

// round 5
// speedup vs baseline: 1.0666x; 1.0408x over previous
#include <cuda_runtime.h>
#include <cuda_fp16.h>
#include <cuda_bf16.h>
#include <mma.h>
#include <cstdint>

using namespace nvcuda;

#define N_NODES 50000
#define E_EDGES 800000
#define IN_SZ   256
#define HID     128
#define OUT_SZ  40
#define OUT_PAD 64
#define NUM_STEPS 16
#define LAM   1.0f
#define ALPHA 0.5f

// ---------------- scratch (static device globals; no allocation) ----------------
__device__ __half g_Xh[N_NODES * IN_SZ];     // fp16 copy of X
__device__ __half g_W1h[IN_SZ * HID];
__device__ __half g_W2h[HID * HID];
__device__ __half g_WoutPh[HID * OUT_PAD];   // Wout zero-padded to 64 cols
__device__ __half g_H1h[N_NODES * HID];      // relu(X@W1+b1) in fp16
__device__ float  g_Y0[N_NODES * HID];       // MLP output / anchor
__device__ float  g_Ya[N_NODES * HID];       // fp32 state ping
__device__ float  g_Yb[N_NODES * HID];       // fp32 state pong
__device__ __half g_Ha[N_NODES * HID];       // fp16 gather copy ping
__device__ __half g_Hb[N_NODES * HID];       // fp16 gather copy pong
__device__ int    g_deg[N_NODES];
__device__ int    g_rowptr[N_NODES + 1];
__device__ int    g_fill[N_NODES];
__device__ int    g_csrcol[E_EDGES];
__device__ float  g_invd[N_NODES];

// ---------------- CSR build ----------------
__global__ void zero_deg_kernel() {
    int i = blockIdx.x * blockDim.x + threadIdx.x;
    if (i < N_NODES) g_deg[i] = 0;
}

__global__ void count_edges_kernel(const int* __restrict__ row) {
    for (int e = blockIdx.x * blockDim.x + threadIdx.x; e < E_EDGES;
         e += gridDim.x * blockDim.x) {
        atomicAdd(&g_deg[row[e]], 1);
    }
}

__global__ void scan_kernel() {
    __shared__ int wsum[32];
    __shared__ int carry_s;
    int tid = threadIdx.x;
    int lane = tid & 31;
    int wid = tid >> 5;
    if (tid == 0) carry_s = 0;
    __syncthreads();

    for (int base = 0; base < N_NODES; base += 1024) {
        int i = base + tid;
        int v = (i < N_NODES) ? g_deg[i] : 0;
        int x = v;
        #pragma unroll
        for (int off = 1; off < 32; off <<= 1) {
            int t = __shfl_up_sync(0xffffffffu, x, off);
            if (lane >= off) x += t;
        }
        if (lane == 31) wsum[wid] = x;
        __syncthreads();
        if (wid == 0) {
            int s = wsum[lane];
            #pragma unroll
            for (int off = 1; off < 32; off <<= 1) {
                int t = __shfl_up_sync(0xffffffffu, s, off);
                if (lane >= off) s += t;
            }
            wsum[lane] = s;
        }
        __syncthreads();
        int woff = (wid == 0) ? 0 : wsum[wid - 1];
        int excl = carry_s + woff + x - v;
        if (i < N_NODES) {
            g_rowptr[i] = excl;
            g_fill[i]   = excl;
            g_invd[i]   = 1.0f / (LAM * (float)v + 1.0f);
        }
        __syncthreads();
        if (tid == 0) carry_s += wsum[31];
        __syncthreads();
    }
    if (tid == 0) g_rowptr[N_NODES] = E_EDGES;
}

__global__ void scatter_edges_kernel(const int* __restrict__ row,
                                     const int* __restrict__ col) {
    for (int e = blockIdx.x * blockDim.x + threadIdx.x; e < E_EDGES;
         e += gridDim.x * blockDim.x) {
        int r = row[e];
        int p = atomicAdd(&g_fill[r], 1);
        g_csrcol[p] = col[e];
    }
}

// ---------------- fp32 -> fp16 conversion (vectorized x4) ----------------
__global__ void f2h_kernel(const float4* __restrict__ src,
                           uint2* __restrict__ dst, int n4) {
    int i = blockIdx.x * blockDim.x + threadIdx.x;
    if (i >= n4) return;
    float4 v = src[i];
    __half2 h01 = __float22half2_rn(make_float2(v.x, v.y));
    __half2 h23 = __float22half2_rn(make_float2(v.z, v.w));
    uint2 u;
    u.x = *reinterpret_cast<unsigned int*>(&h01);
    u.y = *reinterpret_cast<unsigned int*>(&h23);
    dst[i] = u;
}

__global__ void pad_wout_kernel(const float* __restrict__ Wout) {
    int i = blockIdx.x * blockDim.x + threadIdx.x;   // 128*64
    if (i >= HID * OUT_PAD) return;
    int r = i / OUT_PAD;
    int c = i % OUT_PAD;
    g_WoutPh[i] = (c < OUT_SZ) ? __float2half_rn(Wout[r * OUT_SZ + c]) : __half(0.f);
}

// ---------------- fused SpMM + TWIRLS update (high-MLP gather) ----------------
__device__ __forceinline__ float4 h4_to_f4(uint2 u) {
    float2 a = __half22float2(*reinterpret_cast<__half2*>(&u.x));
    float2 b = __half22float2(*reinterpret_cast<__half2*>(&u.y));
    return make_float4(a.x, a.y, b.x, b.y);
}

__global__ void __launch_bounds__(256)
spmm_step_kernel(const float4* __restrict__ Yin,
                 const uint2*  __restrict__ Hin,
                 float4*       __restrict__ Yout,
                 uint2*        __restrict__ Hout) {
    int w    = (blockIdx.x * blockDim.x + threadIdx.x) >> 5;
    int lane = threadIdx.x & 31;
    if (w >= N_NODES) return;

    int s = g_rowptr[w];
    int e = g_rowptr[w + 1];

    // prefetch own state early (overlaps with gather latency)
    float4 y  = Yin[(size_t)w * 32 + lane];
    float4 y0 = reinterpret_cast<const float4*>(g_Y0)[(size_t)w * 32 + lane];
    float aid = ALPHA * g_invd[w];

    float4 acc = make_float4(0.f, 0.f, 0.f, 0.f);
    for (int base = s; base < e; base += 32) {
        int chunk = min(32, e - base);
        int cj = g_csrcol[base + ((chunk == 32) ? lane : min(lane, chunk - 1))];

        int k = 0;
        int c8 = chunk & ~7;
        for (; k < c8; k += 8) {
            int j0 = __shfl_sync(0xffffffffu, cj, k + 0);
            int j1 = __shfl_sync(0xffffffffu, cj, k + 1);
            int j2 = __shfl_sync(0xffffffffu, cj, k + 2);
            int j3 = __shfl_sync(0xffffffffu, cj, k + 3);
            int j4 = __shfl_sync(0xffffffffu, cj, k + 4);
            int j5 = __shfl_sync(0xffffffffu, cj, k + 5);
            int j6 = __shfl_sync(0xffffffffu, cj, k + 6);
            int j7 = __shfl_sync(0xffffffffu, cj, k + 7);
            uint2 u0 = Hin[(size_t)j0 * 32 + lane];
            uint2 u1 = Hin[(size_t)j1 * 32 + lane];
            uint2 u2 = Hin[(size_t)j2 * 32 + lane];
            uint2 u3 = Hin[(size_t)j3 * 32 + lane];
            uint2 u4 = Hin[(size_t)j4 * 32 + lane];
            uint2 u5 = Hin[(size_t)j5 * 32 + lane];
            uint2 u6 = Hin[(size_t)j6 * 32 + lane];
            uint2 u7 = Hin[(size_t)j7 * 32 + lane];
            float4 v0 = h4_to_f4(u0), v1 = h4_to_f4(u1);
            float4 v2 = h4_to_f4(u2), v3 = h4_to_f4(u3);
            float4 v4 = h4_to_f4(u4), v5 = h4_to_f4(u5);
            float4 v6 = h4_to_f4(u6), v7 = h4_to_f4(u7);
            acc.x += ((v0.x + v1.x) + (v2.x + v3.x)) + ((v4.x + v5.x) + (v6.x + v7.x));
            acc.y += ((v0.y + v1.y) + (v2.y + v3.y)) + ((v4.y + v5.y) + (v6.y + v7.y));
            acc.z += ((v0.z + v1.z) + (v2.z + v3.z)) + ((v4.z + v5.z) + (v6.z + v7.z));
            acc.w += ((v0.w + v1.w) + (v2.w + v3.w)) + ((v4.w + v5.w) + (v6.w + v7.w));
        }
        int c4 = chunk & ~3;
        for (; k < c4; k += 4) {
            int j0 = __shfl_sync(0xffffffffu, cj, k + 0);
            int j1 = __shfl_sync(0xffffffffu, cj, k + 1);
            int j2 = __shfl_sync(0xffffffffu, cj, k + 2);
            int j3 = __shfl_sync(0xffffffffu, cj, k + 3);
            uint2 u0 = Hin[(size_t)j0 * 32 + lane];
            uint2 u1 = Hin[(size_t)j1 * 32 + lane];
            uint2 u2 = Hin[(size_t)j2 * 32 + lane];
            uint2 u3 = Hin[(size_t)j3 * 32 + lane];
            float4 v0 = h4_to_f4(u0), v1 = h4_to_f4(u1);
            float4 v2 = h4_to_f4(u2), v3 = h4_to_f4(u3);
            acc.x += (v0.x + v1.x) + (v2.x + v3.x);
            acc.y += (v0.y + v1.y) + (v2.y + v3.y);
            acc.z += (v0.z + v1.z) + (v2.z + v3.z);
            acc.w += (v0.w + v1.w) + (v2.w + v3.w);
        }
        for (; k < chunk; ++k) {
            int j0 = __shfl_sync(0xffffffffu, cj, k);
            float4 v0 = h4_to_f4(Hin[(size_t)j0 * 32 + lane]);
            acc.x += v0.x; acc.y += v0.y; acc.z += v0.z; acc.w += v0.w;
        }
    }

    float4 o;
    o.x = (1.0f - ALPHA) * y.x + aid * (LAM * acc.x + y0.x);
    o.y = (1.0f - ALPHA) * y.y + aid * (LAM * acc.y + y0.y);
    o.z = (1.0f - ALPHA) * y.z + aid * (LAM * acc.z + y0.z);
    o.w = (1.0f - ALPHA) * y.w + aid * (LAM * acc.w + y0.w);
    Yout[(size_t)w * 32 + lane] = o;

    __half2 h01 = __float22half2_rn(make_float2(o.x, o.y));
    __half2 h23 = __float22half2_rn(make_float2(o.z, o.w));
    uint2 hu;
    hu.x = *reinterpret_cast<unsigned int*>(&h01);
    hu.y = *reinterpret_cast<unsigned int*>(&h23);
    Hout[(size_t)w * 32 + lane] = hu;
}

// ---------------- fp16 tensor-core GEMM (wmma), fp32 accum ----------------
// C[M,Nc] = epilogue(A[M,K] @ B[K,Nc] + bias)
// MODE 0: relu, write half out (Ch)              (GEMM1: X@W1 -> H1h)
// MODE 1: write fp32 out (C) + half mirror (Ch)  (GEMM2: H1@W2 -> Y0, Ha)
// MODE 2: write fp32 out (C) with col guard < OUT_SZ, row stride OUT_SZ
template <int MODE>
__global__ void __launch_bounds__(128)
wmma_gemm_kernel(const __half* __restrict__ A,
                 const __half* __restrict__ B,
                 const float* __restrict__ bias,
                 float* __restrict__ C,
                 __half* __restrict__ Ch,
                 int M, int K, int Nc) {
    const int BM = 64, BN = 64, BK = 32;
    __shared__ __align__(16) __half As[BM][BK + 16];   // row stride 48 halves
    __shared__ __align__(16) __half Bs[BK][BN + 8];    // row stride 72 halves
    __shared__ __align__(16) float  Cs[BM][BN];

    int tid = threadIdx.x;
    int wid = tid >> 5;
    int wr = wid >> 1;    // 0..1 (32-row strip)
    int wc = wid & 1;     // 0..1 (32-col strip)
    int bm = blockIdx.x * BM;
    int bn = blockIdx.y * BN;

    wmma::fragment<wmma::accumulator, 16, 16, 16, float> cf[2][2];
    #pragma unroll
    for (int i = 0; i < 2; ++i)
        #pragma unroll
        for (int j = 0; j < 2; ++j)
            wmma::fill_fragment(cf[i][j], 0.0f);

    for (int k0 = 0; k0 < K; k0 += BK) {
        // A tile: 64x32 halves, 16B chunks (8 halves). 256 chunks / 128 thr = 2 each.
        #pragma unroll
        for (int l = 0; l < 2; ++l) {
            int c  = tid + l * 128;
            int r  = c >> 2;
            int cc = (c & 3) * 8;
            int gr = bm + r;
            uint4 v = make_uint4(0, 0, 0, 0);
            if (gr < M)
                v = *reinterpret_cast<const uint4*>(&A[(size_t)gr * K + k0 + cc]);
            *reinterpret_cast<uint4*>(&As[r][cc]) = v;
        }
        // B tile: 32x64 halves. 256 chunks.
        #pragma unroll
        for (int l = 0; l < 2; ++l) {
            int c  = tid + l * 128;
            int r  = c >> 3;
            int cc = (c & 7) * 8;
            uint4 v = *reinterpret_cast<const uint4*>(&B[(size_t)(k0 + r) * Nc + bn + cc]);
            *reinterpret_cast<uint4*>(&Bs[r][cc]) = v;
        }
        __syncthreads();

        #pragma unroll
        for (int kk = 0; kk < 2; ++kk) {
            wmma::fragment<wmma::matrix_a, 16, 16, 16, __half, wmma::row_major> af[2];
            wmma::fragment<wmma::matrix_b, 16, 16, 16, __half, wmma::row_major> bf[2];
            #pragma unroll
            for (int i = 0; i < 2; ++i)
                wmma::load_matrix_sync(af[i], &As[wr * 32 + i * 16][kk * 16], BK + 16);
            #pragma unroll
            for (int j = 0; j < 2; ++j)
                wmma::load_matrix_sync(bf[j], &Bs[kk * 16][wc * 32 + j * 16], BN + 8);
            #pragma unroll
            for (int i = 0; i < 2; ++i)
                #pragma unroll
                for (int j = 0; j < 2; ++j)
                    wmma::mma_sync(cf[i][j], af[i], bf[j], cf[i][j]);
        }
        __syncthreads();
    }

    #pragma unroll
    for (int i = 0; i < 2; ++i)
        #pragma unroll
        for (int j = 0; j < 2; ++j)
            wmma::store_matrix_sync(&Cs[wr * 32 + i * 16][wc * 32 + j * 16],
                                    cf[i][j], BN, wmma::mem_row_major);
    __syncthreads();

    // epilogue: 4096 elems / 128 threads = 32 each
    #pragma unroll 8
    for (int l = 0; l < 32; ++l) {
        int idx = tid + l * 128;
        int r  = idx >> 6;
        int cc = idx & 63;
        int gr = bm + r;
        if (gr >= M) continue;
        int gc = bn + cc;
        if (MODE == 2) {
            if (gc < OUT_SZ)
                C[(size_t)gr * OUT_SZ + gc] = Cs[r][cc] + bias[gc];
        } else {
            float v = Cs[r][cc] + bias[gc];
            if (MODE == 0) {
                v = fmaxf(v, 0.f);
                Ch[(size_t)gr * Nc + gc] = __float2half_rn(v);
            } else {  // MODE 1
                C[(size_t)gr * Nc + gc]  = v;
                Ch[(size_t)gr * Nc + gc] = __float2half_rn(v);
            }
        }
    }
}

// ---------------- launch ----------------
extern "C" void kernel_launch(void* const* d_in, const int* in_sizes, int n_in,
                              void* d_out, int out_size) {
    const float* X    = (const float*)d_in[0];
    const int*   row  = (const int*)d_in[1];
    const int*   col  = (const int*)d_in[2];
    const float* W1   = (const float*)d_in[3];
    const float* b1   = (const float*)d_in[4];
    const float* W2   = (const float*)d_in[5];
    const float* b2   = (const float*)d_in[6];
    const float* Wout = (const float*)d_in[7];
    const float* bout = (const float*)d_in[8];
    float*       out  = (float*)d_out;

    __half *pXh, *pW1h, *pW2h, *pH1h, *pHa, *pHb, *pWoutPh;
    float  *pY0, *pYa, *pYb;
    cudaGetSymbolAddress((void**)&pXh,  g_Xh);
    cudaGetSymbolAddress((void**)&pW1h, g_W1h);
    cudaGetSymbolAddress((void**)&pW2h, g_W2h);
    cudaGetSymbolAddress((void**)&pH1h, g_H1h);
    cudaGetSymbolAddress((void**)&pY0,  g_Y0);
    cudaGetSymbolAddress((void**)&pYa,  g_Ya);
    cudaGetSymbolAddress((void**)&pYb,  g_Yb);
    cudaGetSymbolAddress((void**)&pHa,  g_Ha);
    cudaGetSymbolAddress((void**)&pHb,  g_Hb);
    cudaGetSymbolAddress((void**)&pWoutPh, g_WoutPh);

    // CSR build
    zero_deg_kernel<<<(N_NODES + 255) / 256, 256>>>();
    count_edges_kernel<<<1024, 256>>>(row);
    scan_kernel<<<1, 1024>>>();
    scatter_edges_kernel<<<1024, 256>>>(row, col);

    // fp16 conversions
    {
        int n4 = N_NODES * IN_SZ / 4;
        f2h_kernel<<<(n4 + 255) / 256, 256>>>(
            reinterpret_cast<const float4*>(X), reinterpret_cast<uint2*>(pXh), n4);
        int w1n4 = IN_SZ * HID / 4;
        f2h_kernel<<<(w1n4 + 255) / 256, 256>>>(
            reinterpret_cast<const float4*>(W1), reinterpret_cast<uint2*>(pW1h), w1n4);
        int w2n4 = HID * HID / 4;
        f2h_kernel<<<(w2n4 + 255) / 256, 256>>>(
            reinterpret_cast<const float4*>(W2), reinterpret_cast<uint2*>(pW2h), w2n4);
        pad_wout_kernel<<<(HID * OUT_PAD + 255) / 256, 256>>>(Wout);
    }

    // MLP on tensor cores
    dim3 g1((N_NODES + 63) / 64, HID / 64);
    wmma_gemm_kernel<0><<<g1, 128>>>(pXh, pW1h, b1, nullptr, pH1h,
                                     N_NODES, IN_SZ, HID);
    wmma_gemm_kernel<1><<<g1, 128>>>(pH1h, pW2h, b2, pY0, pHa,
                                     N_NODES, HID, HID);

    // 16 propagation steps, ping-pong (fp32 state + fp16 gather copy)
    const int spmm_blocks = (N_NODES * 32 + 255) / 256;
    const float*  yin = pY0;
    const __half* hin = pHa;
    for (int k = 0; k < NUM_STEPS; ++k) {
        float*  yout = (k & 1) ? pYb : pYa;
        __half* hout = (k & 1) ? pHa : pHb;
        spmm_step_kernel<<<spmm_blocks, 256>>>(
            reinterpret_cast<const float4*>(yin),
            reinterpret_cast<const uint2*>(hin),
            reinterpret_cast<float4*>(yout),
            reinterpret_cast<uint2*>(hout));
        yin = yout;
        hin = hout;
    }

    // output projection from the fp16 mirror
    dim3 g3((N_NODES + 63) / 64, 1);
    wmma_gemm_kernel<2><<<g3, 128>>>(hin, pWoutPh, bout, out, nullptr,
                                     N_NODES, HID, OUT_PAD);
}

// round 8
// speedup vs baseline: 1.7067x; 1.6000x over previous
#include <cuda_runtime.h>
#include <cuda_fp16.h>
#include <cuda_bf16.h>
#include <mma.h>
#include <cstdint>

using namespace nvcuda;

#define N_NODES 50000
#define E_EDGES 800000
#define IN_SZ   256
#define HID     128
#define OUT_SZ  40
#define ZW      64        // padded propagation width (40 real + 24 zeros)
#define NUM_STEPS 16
#define LAM   1.0f
#define ALPHA 0.5f
#define SCAN_BLOCKS ((N_NODES + 1023) / 1024)

// ---------------- scratch (static device globals; no allocation) ----------------
__device__ __half g_W1h[IN_SZ * HID];
__device__ __half g_W2h[HID * HID];
__device__ __half g_WoutPh[HID * ZW];        // Wout zero-padded to 64 cols
__device__ __half g_H1h[N_NODES * HID];      // relu(X@W1+b1) fp16
__device__ __half g_Y0h[N_NODES * HID];      // MLP output fp16
__device__ float  g_Z0[N_NODES * ZW];        // anchor Z0 = Y0 @ WoutP (fp32)
__device__ float  g_Zfa[N_NODES * ZW];       // fp32 state ping
__device__ float  g_Zfb[N_NODES * ZW];       // fp32 state pong
__device__ __half g_Zha[N_NODES * ZW];       // fp16 gather mirror ping
__device__ __half g_Zhb[N_NODES * ZW];       // fp16 gather mirror pong
__device__ int    g_deg[N_NODES];
__device__ int    g_rowptr[N_NODES + 1];
__device__ int    g_fill[N_NODES];
__device__ int    g_csrcol[E_EDGES];
__device__ float  g_invd[N_NODES];
__device__ int    g_bsum[SCAN_BLOCKS];
__device__ int    g_boff[SCAN_BLOCKS];

// ---------------- CSR build ----------------
__global__ void zero_deg_kernel() {
    int i = blockIdx.x * blockDim.x + threadIdx.x;
    if (i < N_NODES) g_deg[i] = 0;
}

__global__ void count_edges_kernel(const int* __restrict__ row) {
    for (int e = blockIdx.x * blockDim.x + threadIdx.x; e < E_EDGES;
         e += gridDim.x * blockDim.x) {
        atomicAdd(&g_deg[row[e]], 1);
    }
}

// phase 1: per-block exclusive scan of deg -> rowptr (in-block), block sums
__global__ void scan_block_kernel() {
    __shared__ int wsum[32];
    int tid = threadIdx.x;
    int lane = tid & 31;
    int wid = tid >> 5;
    int i = blockIdx.x * 1024 + tid;
    int v = (i < N_NODES) ? g_deg[i] : 0;
    int x = v;
    #pragma unroll
    for (int off = 1; off < 32; off <<= 1) {
        int t = __shfl_up_sync(0xffffffffu, x, off);
        if (lane >= off) x += t;
    }
    if (lane == 31) wsum[wid] = x;
    __syncthreads();
    if (wid == 0) {
        int s = wsum[lane];
        #pragma unroll
        for (int off = 1; off < 32; off <<= 1) {
            int t = __shfl_up_sync(0xffffffffu, s, off);
            if (lane >= off) s += t;
        }
        wsum[lane] = s;
    }
    __syncthreads();
    int woff = (wid == 0) ? 0 : wsum[wid - 1];
    if (i < N_NODES) g_rowptr[i] = woff + x - v;   // in-block exclusive
    if (tid == 0) g_bsum[blockIdx.x] = wsum[31];
}

// phase 2: scan block sums (single small block)
__global__ void scan_sums_kernel() {
    __shared__ int s[64];
    int t = threadIdx.x;
    s[t] = (t < SCAN_BLOCKS) ? g_bsum[t] : 0;
    __syncthreads();
    #pragma unroll
    for (int off = 1; off < 64; off <<= 1) {
        int v = (t >= off) ? s[t - off] : 0;
        __syncthreads();
        s[t] += v;
        __syncthreads();
    }
    if (t < SCAN_BLOCKS) g_boff[t] = s[t] - g_bsum[t];  // exclusive
    if (t == 0) g_rowptr[N_NODES] = E_EDGES;
}

// phase 3: apply block offsets, init fill + invd
__global__ void scan_apply_kernel() {
    int i = blockIdx.x * 1024 + threadIdx.x;
    if (i >= N_NODES) return;
    int rp = g_rowptr[i] + g_boff[blockIdx.x];
    g_rowptr[i] = rp;
    g_fill[i]   = rp;
    g_invd[i]   = 1.0f / (LAM * (float)g_deg[i] + 1.0f);
}

__global__ void scatter_edges_kernel(const int* __restrict__ row,
                                     const int* __restrict__ col) {
    for (int e = blockIdx.x * blockDim.x + threadIdx.x; e < E_EDGES;
         e += gridDim.x * blockDim.x) {
        int r = row[e];
        int p = atomicAdd(&g_fill[r], 1);
        g_csrcol[p] = col[e];
    }
}

// ---------------- small weight conversions (one kernel) ----------------
#define W1_U2 (IN_SZ * HID / 4)     // 8192
#define W2_U2 (HID * HID / 4)       // 4096
#define WOUTP (HID * ZW)            // 8192
__global__ void conv_weights_kernel(const float* __restrict__ W1,
                                    const float* __restrict__ W2,
                                    const float* __restrict__ Wout) {
    int i = blockIdx.x * blockDim.x + threadIdx.x;
    if (i < W1_U2) {
        float4 v = reinterpret_cast<const float4*>(W1)[i];
        __half2 a = __float22half2_rn(make_float2(v.x, v.y));
        __half2 b = __float22half2_rn(make_float2(v.z, v.w));
        uint2 u;
        u.x = *reinterpret_cast<unsigned int*>(&a);
        u.y = *reinterpret_cast<unsigned int*>(&b);
        reinterpret_cast<uint2*>(g_W1h)[i] = u;
    } else if (i < W1_U2 + W2_U2) {
        int j = i - W1_U2;
        float4 v = reinterpret_cast<const float4*>(W2)[j];
        __half2 a = __float22half2_rn(make_float2(v.x, v.y));
        __half2 b = __float22half2_rn(make_float2(v.z, v.w));
        uint2 u;
        u.x = *reinterpret_cast<unsigned int*>(&a);
        u.y = *reinterpret_cast<unsigned int*>(&b);
        reinterpret_cast<uint2*>(g_W2h)[j] = u;
    } else if (i < W1_U2 + W2_U2 + WOUTP) {
        int j = i - W1_U2 - W2_U2;
        int r = j / ZW;
        int c = j % ZW;
        g_WoutPh[j] = (c < OUT_SZ) ? __float2half_rn(Wout[r * OUT_SZ + c])
                                   : __half(0.f);
    }
}

// ---------------- fp16 tensor-core GEMM (wmma), fp32 accum ----------------
// MODE 0: relu, write half out Ch                 (GEMM1: X@W1 -> H1h)
// MODE 1: write half out Ch                       (GEMM2: H1h@W2 -> Y0h)
// MODE 2: no bias; write fp32 C (anchor) + fp32 C2 (state) + half Ch (mirror)
// AF32:   A source is fp32 (converted during tile load)
template <int MODE, bool AF32>
__global__ void __launch_bounds__(128)
wmma_gemm_kernel(const void* __restrict__ Araw,
                 const __half* __restrict__ B,
                 const float* __restrict__ bias,
                 float* __restrict__ C,
                 float* __restrict__ C2,
                 __half* __restrict__ Ch,
                 int M, int K, int Nc) {
    const int BM = 64, BN = 64, BK = 32;
    __shared__ __align__(16) __half As[BM][BK + 16];
    __shared__ __align__(16) __half Bs[BK][BN + 8];
    __shared__ __align__(16) float  Cs[BM][BN];

    int tid = threadIdx.x;
    int wid = tid >> 5;
    int wr = wid >> 1;
    int wc = wid & 1;
    int bm = blockIdx.x * BM;
    int bn = blockIdx.y * BN;

    wmma::fragment<wmma::accumulator, 16, 16, 16, float> cf[2][2];
    #pragma unroll
    for (int i = 0; i < 2; ++i)
        #pragma unroll
        for (int j = 0; j < 2; ++j)
            wmma::fill_fragment(cf[i][j], 0.0f);

    for (int k0 = 0; k0 < K; k0 += BK) {
        if (AF32) {
            const float* A = (const float*)Araw;
            #pragma unroll
            for (int l = 0; l < 4; ++l) {
                int c  = tid + l * 128;
                int r  = c >> 3;
                int c4 = (c & 7) * 4;
                int gr = bm + r;
                float4 v = make_float4(0.f, 0.f, 0.f, 0.f);
                if (gr < M)
                    v = *reinterpret_cast<const float4*>(&A[(size_t)gr * K + k0 + c4]);
                __half2 h0 = __float22half2_rn(make_float2(v.x, v.y));
                __half2 h1 = __float22half2_rn(make_float2(v.z, v.w));
                *reinterpret_cast<__half2*>(&As[r][c4 + 0]) = h0;
                *reinterpret_cast<__half2*>(&As[r][c4 + 2]) = h1;
            }
        } else {
            const __half* A = (const __half*)Araw;
            #pragma unroll
            for (int l = 0; l < 2; ++l) {
                int c  = tid + l * 128;
                int r  = c >> 2;
                int cc = (c & 3) * 8;
                int gr = bm + r;
                uint4 v = make_uint4(0, 0, 0, 0);
                if (gr < M)
                    v = *reinterpret_cast<const uint4*>(&A[(size_t)gr * K + k0 + cc]);
                *reinterpret_cast<uint4*>(&As[r][cc]) = v;
            }
        }
        // B tile: 32 x 64 halves = 256 uint4
        #pragma unroll
        for (int l = 0; l < 2; ++l) {
            int c  = tid + l * 128;
            int r  = c >> 3;
            int cc = (c & 7) * 8;
            uint4 v = *reinterpret_cast<const uint4*>(&B[(size_t)(k0 + r) * Nc + bn + cc]);
            *reinterpret_cast<uint4*>(&Bs[r][cc]) = v;
        }
        __syncthreads();

        #pragma unroll
        for (int kk = 0; kk < 2; ++kk) {
            wmma::fragment<wmma::matrix_a, 16, 16, 16, __half, wmma::row_major> af[2];
            wmma::fragment<wmma::matrix_b, 16, 16, 16, __half, wmma::row_major> bf[2];
            #pragma unroll
            for (int i = 0; i < 2; ++i)
                wmma::load_matrix_sync(af[i], &As[wr * 32 + i * 16][kk * 16], BK + 16);
            #pragma unroll
            for (int j = 0; j < 2; ++j)
                wmma::load_matrix_sync(bf[j], &Bs[kk * 16][wc * 32 + j * 16], BN + 8);
            #pragma unroll
            for (int i = 0; i < 2; ++i)
                #pragma unroll
                for (int j = 0; j < 2; ++j)
                    wmma::mma_sync(cf[i][j], af[i], bf[j], cf[i][j]);
        }
        __syncthreads();
    }

    #pragma unroll
    for (int i = 0; i < 2; ++i)
        #pragma unroll
        for (int j = 0; j < 2; ++j)
            wmma::store_matrix_sync(&Cs[wr * 32 + i * 16][wc * 32 + j * 16],
                                    cf[i][j], BN, wmma::mem_row_major);
    __syncthreads();

    #pragma unroll 8
    for (int l = 0; l < 32; ++l) {
        int idx = tid + l * 128;
        int r  = idx >> 6;
        int cc = idx & 63;
        int gr = bm + r;
        if (gr >= M) continue;
        int gc = bn + cc;
        if (MODE == 2) {
            float v = Cs[r][cc];
            C[(size_t)gr * Nc + gc]  = v;
            C2[(size_t)gr * Nc + gc] = v;
            Ch[(size_t)gr * Nc + gc] = __float2half_rn(v);
        } else {
            float v = Cs[r][cc] + bias[gc];
            if (MODE == 0) v = fmaxf(v, 0.f);
            Ch[(size_t)gr * Nc + gc] = __float2half_rn(v);
        }
    }
}

// ---------------- fused SpMM + TWIRLS update on Z (width 64) ----------------
// One warp per row. Lane owns 2 features (float2 / half2).
// Gather = one LDG.32 per warp per edge: 32 lanes x 4B = 128B = 1 cacheline.
__global__ void __launch_bounds__(256)
spmm_z_kernel(const float2* __restrict__ Yin,
              const unsigned int* __restrict__ Hin,
              float2* __restrict__ Yout,
              unsigned int* __restrict__ Hout,
              const float2* __restrict__ Z0,
              float2* __restrict__ outZ,      // [N,20] float2 when final
              const float2* __restrict__ bout2,
              int writeOut) {
    int w    = (blockIdx.x * blockDim.x + threadIdx.x) >> 5;
    int lane = threadIdx.x & 31;
    if (w >= N_NODES) return;

    int s = g_rowptr[w];
    int e = g_rowptr[w + 1];

    float2 y  = Yin[(size_t)w * 32 + lane];
    float2 z0 = Z0[(size_t)w * 32 + lane];
    float aid = ALPHA * g_invd[w];

    float2 acc = make_float2(0.f, 0.f);
    for (int base = s; base < e; base += 32) {
        int chunk = min(32, e - base);
        int cj = g_csrcol[base + ((chunk == 32) ? lane : min(lane, chunk - 1))];

        int k = 0;
        int c8 = chunk & ~7;
        for (; k < c8; k += 8) {
            int j0 = __shfl_sync(0xffffffffu, cj, k + 0);
            int j1 = __shfl_sync(0xffffffffu, cj, k + 1);
            int j2 = __shfl_sync(0xffffffffu, cj, k + 2);
            int j3 = __shfl_sync(0xffffffffu, cj, k + 3);
            int j4 = __shfl_sync(0xffffffffu, cj, k + 4);
            int j5 = __shfl_sync(0xffffffffu, cj, k + 5);
            int j6 = __shfl_sync(0xffffffffu, cj, k + 6);
            int j7 = __shfl_sync(0xffffffffu, cj, k + 7);
            unsigned int u0 = Hin[(size_t)j0 * 32 + lane];
            unsigned int u1 = Hin[(size_t)j1 * 32 + lane];
            unsigned int u2 = Hin[(size_t)j2 * 32 + lane];
            unsigned int u3 = Hin[(size_t)j3 * 32 + lane];
            unsigned int u4 = Hin[(size_t)j4 * 32 + lane];
            unsigned int u5 = Hin[(size_t)j5 * 32 + lane];
            unsigned int u6 = Hin[(size_t)j6 * 32 + lane];
            unsigned int u7 = Hin[(size_t)j7 * 32 + lane];
            float2 v0 = __half22float2(*reinterpret_cast<__half2*>(&u0));
            float2 v1 = __half22float2(*reinterpret_cast<__half2*>(&u1));
            float2 v2 = __half22float2(*reinterpret_cast<__half2*>(&u2));
            float2 v3 = __half22float2(*reinterpret_cast<__half2*>(&u3));
            float2 v4 = __half22float2(*reinterpret_cast<__half2*>(&u4));
            float2 v5 = __half22float2(*reinterpret_cast<__half2*>(&u5));
            float2 v6 = __half22float2(*reinterpret_cast<__half2*>(&u6));
            float2 v7 = __half22float2(*reinterpret_cast<__half2*>(&u7));
            acc.x += ((v0.x + v1.x) + (v2.x + v3.x)) + ((v4.x + v5.x) + (v6.x + v7.x));
            acc.y += ((v0.y + v1.y) + (v2.y + v3.y)) + ((v4.y + v5.y) + (v6.y + v7.y));
        }
        int c4 = chunk & ~3;
        for (; k < c4; k += 4) {
            int j0 = __shfl_sync(0xffffffffu, cj, k + 0);
            int j1 = __shfl_sync(0xffffffffu, cj, k + 1);
            int j2 = __shfl_sync(0xffffffffu, cj, k + 2);
            int j3 = __shfl_sync(0xffffffffu, cj, k + 3);
            unsigned int u0 = Hin[(size_t)j0 * 32 + lane];
            unsigned int u1 = Hin[(size_t)j1 * 32 + lane];
            unsigned int u2 = Hin[(size_t)j2 * 32 + lane];
            unsigned int u3 = Hin[(size_t)j3 * 32 + lane];
            float2 v0 = __half22float2(*reinterpret_cast<__half2*>(&u0));
            float2 v1 = __half22float2(*reinterpret_cast<__half2*>(&u1));
            float2 v2 = __half22float2(*reinterpret_cast<__half2*>(&u2));
            float2 v3 = __half22float2(*reinterpret_cast<__half2*>(&u3));
            acc.x += (v0.x + v1.x) + (v2.x + v3.x);
            acc.y += (v0.y + v1.y) + (v2.y + v3.y);
        }
        for (; k < chunk; ++k) {
            int j0 = __shfl_sync(0xffffffffu, cj, k);
            unsigned int u0 = Hin[(size_t)j0 * 32 + lane];
            float2 v0 = __half22float2(*reinterpret_cast<__half2*>(&u0));
            acc.x += v0.x; acc.y += v0.y;
        }
    }

    float2 o;
    o.x = (1.0f - ALPHA) * y.x + aid * (LAM * acc.x + z0.x);
    o.y = (1.0f - ALPHA) * y.y + aid * (LAM * acc.y + z0.y);

    if (!writeOut) {
        Yout[(size_t)w * 32 + lane] = o;
        __half2 hh = __float22half2_rn(o);
        Hout[(size_t)w * 32 + lane] = *reinterpret_cast<unsigned int*>(&hh);
    } else {
        if (lane < OUT_SZ / 2) {  // 20 float2 = 40 floats
            float2 bb = bout2[lane];
            outZ[(size_t)w * (OUT_SZ / 2) + lane] =
                make_float2(o.x + bb.x, o.y + bb.y);
        }
    }
}

// ---------------- launch ----------------
extern "C" void kernel_launch(void* const* d_in, const int* in_sizes, int n_in,
                              void* d_out, int out_size) {
    const float* X    = (const float*)d_in[0];
    const int*   row  = (const int*)d_in[1];
    const int*   col  = (const int*)d_in[2];
    const float* W1   = (const float*)d_in[3];
    const float* b1   = (const float*)d_in[4];
    const float* W2   = (const float*)d_in[5];
    const float* b2   = (const float*)d_in[6];
    const float* Wout = (const float*)d_in[7];
    const float* bout = (const float*)d_in[8];
    float*       out  = (float*)d_out;

    __half *pW1h, *pW2h, *pWoutPh, *pH1h, *pY0h, *pZha, *pZhb;
    float  *pZ0, *pZfa, *pZfb;
    cudaGetSymbolAddress((void**)&pW1h,   g_W1h);
    cudaGetSymbolAddress((void**)&pW2h,   g_W2h);
    cudaGetSymbolAddress((void**)&pWoutPh, g_WoutPh);
    cudaGetSymbolAddress((void**)&pH1h,   g_H1h);
    cudaGetSymbolAddress((void**)&pY0h,   g_Y0h);
    cudaGetSymbolAddress((void**)&pZ0,    g_Z0);
    cudaGetSymbolAddress((void**)&pZfa,   g_Zfa);
    cudaGetSymbolAddress((void**)&pZfb,   g_Zfb);
    cudaGetSymbolAddress((void**)&pZha,   g_Zha);
    cudaGetSymbolAddress((void**)&pZhb,   g_Zhb);

    // CSR build
    zero_deg_kernel<<<(N_NODES + 255) / 256, 256>>>();
    count_edges_kernel<<<1024, 256>>>(row);
    scan_block_kernel<<<SCAN_BLOCKS, 1024>>>();
    scan_sums_kernel<<<1, 64>>>();
    scan_apply_kernel<<<SCAN_BLOCKS, 1024>>>();
    scatter_edges_kernel<<<1024, 256>>>(row, col);

    // weight conversions (one kernel)
    {
        int tot = W1_U2 + W2_U2 + WOUTP;
        conv_weights_kernel<<<(tot + 255) / 256, 256>>>(W1, W2, Wout);
    }

    // MLP + projection on tensor cores
    dim3 g1((N_NODES + 63) / 64, HID / 64);
    wmma_gemm_kernel<0, true><<<g1, 128>>>(X, pW1h, b1, nullptr, nullptr, pH1h,
                                           N_NODES, IN_SZ, HID);
    wmma_gemm_kernel<1, false><<<g1, 128>>>(pH1h, pW2h, b2, nullptr, nullptr, pY0h,
                                            N_NODES, HID, HID);
    dim3 g2((N_NODES + 63) / 64, 1);
    wmma_gemm_kernel<2, false><<<g2, 128>>>(pY0h, pWoutPh, nullptr, pZ0, pZfa, pZha,
                                            N_NODES, HID, ZW);

    // 16 propagation steps on Z (width 64), ping-pong; last writes out+bout
    const int spmm_blocks = (N_NODES * 32 + 255) / 256;
    const float*  yin = pZfa;
    const __half* hin = pZha;
    for (int k = 0; k < NUM_STEPS; ++k) {
        int final = (k == NUM_STEPS - 1);
        float*  yout = (k & 1) ? pZfa : pZfb;
        __half* hout = (k & 1) ? pZha : pZhb;
        spmm_z_kernel<<<spmm_blocks, 256>>>(
            reinterpret_cast<const float2*>(yin),
            reinterpret_cast<const unsigned int*>(hin),
            reinterpret_cast<float2*>(yout),
            reinterpret_cast<unsigned int*>(hout),
            reinterpret_cast<const float2*>(pZ0),
            reinterpret_cast<float2*>(out),
            reinterpret_cast<const float2*>(bout),
            final);
        yin = yout;
        hin = hout;
    }
}

// round 9
// speedup vs baseline: 1.7080x; 1.0008x over previous
#include <cuda_runtime.h>
#include <cuda_fp16.h>
#include <cuda_bf16.h>
#include <mma.h>
#include <cstdint>

using namespace nvcuda;

#define N_NODES 50000
#define E_EDGES 800000
#define IN_SZ   256
#define HID     128
#define OUT_SZ  40
#define ZW      64        // padded propagation width (40 real + 24 zeros)
#define NUM_STEPS 16
#define LAM   1.0f
#define ALPHA 0.5f
#define SCAN_BLOCKS ((N_NODES + 1023) / 1024)

// ---------------- scratch (static device globals; no allocation) ----------------
__device__ __half g_W1h[IN_SZ * HID];
__device__ __half g_W2h[HID * HID];
__device__ __half g_WoutPh[HID * ZW];        // Wout zero-padded to 64 cols
__device__ __half g_H1h[N_NODES * HID];      // relu(X@W1+b1) fp16
__device__ __half g_Y0h[N_NODES * HID];      // MLP output fp16
__device__ float  g_Z0[N_NODES * ZW];        // anchor Z0 = Y0 @ WoutP (fp32)
__device__ float  g_Zfa[N_NODES * ZW];       // fp32 state ping
__device__ float  g_Zfb[N_NODES * ZW];       // fp32 state pong
__device__ __half g_Zha[N_NODES * ZW];       // fp16 gather mirror ping
__device__ __half g_Zhb[N_NODES * ZW];       // fp16 gather mirror pong
__device__ int    g_deg[N_NODES];
__device__ int    g_rowptr[N_NODES + 1];
__device__ int    g_fill[N_NODES];
__device__ int    g_csrcol[E_EDGES];
__device__ float  g_invd[N_NODES];
__device__ int    g_bsum[SCAN_BLOCKS];
__device__ int    g_boff[SCAN_BLOCKS];

// ---------------- CSR build ----------------
__global__ void zero_deg_kernel() {
    int i = blockIdx.x * blockDim.x + threadIdx.x;
    if (i < N_NODES) g_deg[i] = 0;
}

__global__ void count_edges_kernel(const int* __restrict__ row) {
    for (int e = blockIdx.x * blockDim.x + threadIdx.x; e < E_EDGES;
         e += gridDim.x * blockDim.x) {
        atomicAdd(&g_deg[row[e]], 1);
    }
}

// phase 1: per-block exclusive scan of deg -> rowptr (in-block), block sums
__global__ void scan_block_kernel() {
    __shared__ int wsum[32];
    int tid = threadIdx.x;
    int lane = tid & 31;
    int wid = tid >> 5;
    int i = blockIdx.x * 1024 + tid;
    int v = (i < N_NODES) ? g_deg[i] : 0;
    int x = v;
    #pragma unroll
    for (int off = 1; off < 32; off <<= 1) {
        int t = __shfl_up_sync(0xffffffffu, x, off);
        if (lane >= off) x += t;
    }
    if (lane == 31) wsum[wid] = x;
    __syncthreads();
    if (wid == 0) {
        int s = wsum[lane];
        #pragma unroll
        for (int off = 1; off < 32; off <<= 1) {
            int t = __shfl_up_sync(0xffffffffu, s, off);
            if (lane >= off) s += t;
        }
        wsum[lane] = s;
    }
    __syncthreads();
    int woff = (wid == 0) ? 0 : wsum[wid - 1];
    if (i < N_NODES) g_rowptr[i] = woff + x - v;   // in-block exclusive
    if (tid == 0) g_bsum[blockIdx.x] = wsum[31];
}

// phase 2: scan block sums (single small block)
__global__ void scan_sums_kernel() {
    __shared__ int s[64];
    int t = threadIdx.x;
    s[t] = (t < SCAN_BLOCKS) ? g_bsum[t] : 0;
    __syncthreads();
    #pragma unroll
    for (int off = 1; off < 64; off <<= 1) {
        int v = (t >= off) ? s[t - off] : 0;
        __syncthreads();
        s[t] += v;
        __syncthreads();
    }
    if (t < SCAN_BLOCKS) g_boff[t] = s[t] - g_bsum[t];  // exclusive
    if (t == 0) g_rowptr[N_NODES] = E_EDGES;
}

// phase 3: apply block offsets, init fill + invd
__global__ void scan_apply_kernel() {
    int i = blockIdx.x * 1024 + threadIdx.x;
    if (i >= N_NODES) return;
    int rp = g_rowptr[i] + g_boff[blockIdx.x];
    g_rowptr[i] = rp;
    g_fill[i]   = rp;
    g_invd[i]   = 1.0f / (LAM * (float)g_deg[i] + 1.0f);
}

__global__ void scatter_edges_kernel(const int* __restrict__ row,
                                     const int* __restrict__ col) {
    for (int e = blockIdx.x * blockDim.x + threadIdx.x; e < E_EDGES;
         e += gridDim.x * blockDim.x) {
        int r = row[e];
        int p = atomicAdd(&g_fill[r], 1);
        g_csrcol[p] = col[e];
    }
}

// ---------------- small weight conversions (one kernel) ----------------
#define W1_U2 (IN_SZ * HID / 4)     // 8192
#define W2_U2 (HID * HID / 4)       // 4096
#define WOUTP (HID * ZW)            // 8192
__global__ void conv_weights_kernel(const float* __restrict__ W1,
                                    const float* __restrict__ W2,
                                    const float* __restrict__ Wout) {
    int i = blockIdx.x * blockDim.x + threadIdx.x;
    if (i < W1_U2) {
        float4 v = reinterpret_cast<const float4*>(W1)[i];
        __half2 a = __float22half2_rn(make_float2(v.x, v.y));
        __half2 b = __float22half2_rn(make_float2(v.z, v.w));
        uint2 u;
        u.x = *reinterpret_cast<unsigned int*>(&a);
        u.y = *reinterpret_cast<unsigned int*>(&b);
        reinterpret_cast<uint2*>(g_W1h)[i] = u;
    } else if (i < W1_U2 + W2_U2) {
        int j = i - W1_U2;
        float4 v = reinterpret_cast<const float4*>(W2)[j];
        __half2 a = __float22half2_rn(make_float2(v.x, v.y));
        __half2 b = __float22half2_rn(make_float2(v.z, v.w));
        uint2 u;
        u.x = *reinterpret_cast<unsigned int*>(&a);
        u.y = *reinterpret_cast<unsigned int*>(&b);
        reinterpret_cast<uint2*>(g_W2h)[j] = u;
    } else if (i < W1_U2 + W2_U2 + WOUTP) {
        int j = i - W1_U2 - W2_U2;
        int r = j / ZW;
        int c = j % ZW;
        g_WoutPh[j] = (c < OUT_SZ) ? __float2half_rn(Wout[r * OUT_SZ + c])
                                   : __half(0.f);
    }
}

// ---------------- fp16 tensor-core GEMM (wmma), fp32 accum ----------------
// MODE 0: relu, write half out Ch                 (GEMM1: X@W1 -> H1h)
// MODE 1: write half out Ch                       (GEMM2: H1h@W2 -> Y0h)
// MODE 2: no bias; write fp32 C (anchor) + fp32 C2 (state) + half Ch (mirror)
// AF32:   A source is fp32 (converted during tile load)
template <int MODE, bool AF32>
__global__ void __launch_bounds__(128)
wmma_gemm_kernel(const void* __restrict__ Araw,
                 const __half* __restrict__ B,
                 const float* __restrict__ bias,
                 float* __restrict__ C,
                 float* __restrict__ C2,
                 __half* __restrict__ Ch,
                 int M, int K, int Nc) {
    const int BM = 64, BN = 64, BK = 32;
    __shared__ __align__(16) __half As[BM][BK + 16];
    __shared__ __align__(16) __half Bs[BK][BN + 8];
    __shared__ __align__(16) float  Cs[BM][BN];

    int tid = threadIdx.x;
    int wid = tid >> 5;
    int wr = wid >> 1;
    int wc = wid & 1;
    int bm = blockIdx.x * BM;
    int bn = blockIdx.y * BN;

    wmma::fragment<wmma::accumulator, 16, 16, 16, float> cf[2][2];
    #pragma unroll
    for (int i = 0; i < 2; ++i)
        #pragma unroll
        for (int j = 0; j < 2; ++j)
            wmma::fill_fragment(cf[i][j], 0.0f);

    for (int k0 = 0; k0 < K; k0 += BK) {
        if (AF32) {
            const float* A = (const float*)Araw;
            #pragma unroll
            for (int l = 0; l < 4; ++l) {
                int c  = tid + l * 128;
                int r  = c >> 3;
                int c4 = (c & 7) * 4;
                int gr = bm + r;
                float4 v = make_float4(0.f, 0.f, 0.f, 0.f);
                if (gr < M)
                    v = *reinterpret_cast<const float4*>(&A[(size_t)gr * K + k0 + c4]);
                __half2 h0 = __float22half2_rn(make_float2(v.x, v.y));
                __half2 h1 = __float22half2_rn(make_float2(v.z, v.w));
                *reinterpret_cast<__half2*>(&As[r][c4 + 0]) = h0;
                *reinterpret_cast<__half2*>(&As[r][c4 + 2]) = h1;
            }
        } else {
            const __half* A = (const __half*)Araw;
            #pragma unroll
            for (int l = 0; l < 2; ++l) {
                int c  = tid + l * 128;
                int r  = c >> 2;
                int cc = (c & 3) * 8;
                int gr = bm + r;
                uint4 v = make_uint4(0, 0, 0, 0);
                if (gr < M)
                    v = *reinterpret_cast<const uint4*>(&A[(size_t)gr * K + k0 + cc]);
                *reinterpret_cast<uint4*>(&As[r][cc]) = v;
            }
        }
        // B tile: 32 x 64 halves = 256 uint4
        #pragma unroll
        for (int l = 0; l < 2; ++l) {
            int c  = tid + l * 128;
            int r  = c >> 3;
            int cc = (c & 7) * 8;
            uint4 v = *reinterpret_cast<const uint4*>(&B[(size_t)(k0 + r) * Nc + bn + cc]);
            *reinterpret_cast<uint4*>(&Bs[r][cc]) = v;
        }
        __syncthreads();

        #pragma unroll
        for (int kk = 0; kk < 2; ++kk) {
            wmma::fragment<wmma::matrix_a, 16, 16, 16, __half, wmma::row_major> af[2];
            wmma::fragment<wmma::matrix_b, 16, 16, 16, __half, wmma::row_major> bf[2];
            #pragma unroll
            for (int i = 0; i < 2; ++i)
                wmma::load_matrix_sync(af[i], &As[wr * 32 + i * 16][kk * 16], BK + 16);
            #pragma unroll
            for (int j = 0; j < 2; ++j)
                wmma::load_matrix_sync(bf[j], &Bs[kk * 16][wc * 32 + j * 16], BN + 8);
            #pragma unroll
            for (int i = 0; i < 2; ++i)
                #pragma unroll
                for (int j = 0; j < 2; ++j)
                    wmma::mma_sync(cf[i][j], af[i], bf[j], cf[i][j]);
        }
        __syncthreads();
    }

    #pragma unroll
    for (int i = 0; i < 2; ++i)
        #pragma unroll
        for (int j = 0; j < 2; ++j)
            wmma::store_matrix_sync(&Cs[wr * 32 + i * 16][wc * 32 + j * 16],
                                    cf[i][j], BN, wmma::mem_row_major);
    __syncthreads();

    #pragma unroll 8
    for (int l = 0; l < 32; ++l) {
        int idx = tid + l * 128;
        int r  = idx >> 6;
        int cc = idx & 63;
        int gr = bm + r;
        if (gr >= M) continue;
        int gc = bn + cc;
        if (MODE == 2) {
            float v = Cs[r][cc];
            C[(size_t)gr * Nc + gc]  = v;
            C2[(size_t)gr * Nc + gc] = v;
            Ch[(size_t)gr * Nc + gc] = __float2half_rn(v);
        } else {
            float v = Cs[r][cc] + bias[gc];
            if (MODE == 0) v = fmaxf(v, 0.f);
            Ch[(size_t)gr * Nc + gc] = __float2half_rn(v);
        }
    }
}

// ---------------- fused SpMM + TWIRLS update on Z (width 64) ----------------
// One warp per row. Lane owns 2 features (float2 / half2).
// Gather = one LDG.32 per warp per edge: 32 lanes x 4B = 128B = 1 cacheline.
__global__ void __launch_bounds__(256)
spmm_z_kernel(const float2* __restrict__ Yin,
              const unsigned int* __restrict__ Hin,
              float2* __restrict__ Yout,
              unsigned int* __restrict__ Hout,
              const float2* __restrict__ Z0,
              float2* __restrict__ outZ,      // [N,20] float2 when final
              const float2* __restrict__ bout2,
              int writeOut) {
    int w    = (blockIdx.x * blockDim.x + threadIdx.x) >> 5;
    int lane = threadIdx.x & 31;
    if (w >= N_NODES) return;

    int s = g_rowptr[w];
    int e = g_rowptr[w + 1];

    float2 y  = Yin[(size_t)w * 32 + lane];
    float2 z0 = Z0[(size_t)w * 32 + lane];
    float aid = ALPHA * g_invd[w];

    float2 acc = make_float2(0.f, 0.f);
    for (int base = s; base < e; base += 32) {
        int chunk = min(32, e - base);
        int cj = g_csrcol[base + ((chunk == 32) ? lane : min(lane, chunk - 1))];

        int k = 0;
        int c8 = chunk & ~7;
        for (; k < c8; k += 8) {
            int j0 = __shfl_sync(0xffffffffu, cj, k + 0);
            int j1 = __shfl_sync(0xffffffffu, cj, k + 1);
            int j2 = __shfl_sync(0xffffffffu, cj, k + 2);
            int j3 = __shfl_sync(0xffffffffu, cj, k + 3);
            int j4 = __shfl_sync(0xffffffffu, cj, k + 4);
            int j5 = __shfl_sync(0xffffffffu, cj, k + 5);
            int j6 = __shfl_sync(0xffffffffu, cj, k + 6);
            int j7 = __shfl_sync(0xffffffffu, cj, k + 7);
            unsigned int u0 = Hin[(size_t)j0 * 32 + lane];
            unsigned int u1 = Hin[(size_t)j1 * 32 + lane];
            unsigned int u2 = Hin[(size_t)j2 * 32 + lane];
            unsigned int u3 = Hin[(size_t)j3 * 32 + lane];
            unsigned int u4 = Hin[(size_t)j4 * 32 + lane];
            unsigned int u5 = Hin[(size_t)j5 * 32 + lane];
            unsigned int u6 = Hin[(size_t)j6 * 32 + lane];
            unsigned int u7 = Hin[(size_t)j7 * 32 + lane];
            float2 v0 = __half22float2(*reinterpret_cast<__half2*>(&u0));
            float2 v1 = __half22float2(*reinterpret_cast<__half2*>(&u1));
            float2 v2 = __half22float2(*reinterpret_cast<__half2*>(&u2));
            float2 v3 = __half22float2(*reinterpret_cast<__half2*>(&u3));
            float2 v4 = __half22float2(*reinterpret_cast<__half2*>(&u4));
            float2 v5 = __half22float2(*reinterpret_cast<__half2*>(&u5));
            float2 v6 = __half22float2(*reinterpret_cast<__half2*>(&u6));
            float2 v7 = __half22float2(*reinterpret_cast<__half2*>(&u7));
            acc.x += ((v0.x + v1.x) + (v2.x + v3.x)) + ((v4.x + v5.x) + (v6.x + v7.x));
            acc.y += ((v0.y + v1.y) + (v2.y + v3.y)) + ((v4.y + v5.y) + (v6.y + v7.y));
        }
        int c4 = chunk & ~3;
        for (; k < c4; k += 4) {
            int j0 = __shfl_sync(0xffffffffu, cj, k + 0);
            int j1 = __shfl_sync(0xffffffffu, cj, k + 1);
            int j2 = __shfl_sync(0xffffffffu, cj, k + 2);
            int j3 = __shfl_sync(0xffffffffu, cj, k + 3);
            unsigned int u0 = Hin[(size_t)j0 * 32 + lane];
            unsigned int u1 = Hin[(size_t)j1 * 32 + lane];
            unsigned int u2 = Hin[(size_t)j2 * 32 + lane];
            unsigned int u3 = Hin[(size_t)j3 * 32 + lane];
            float2 v0 = __half22float2(*reinterpret_cast<__half2*>(&u0));
            float2 v1 = __half22float2(*reinterpret_cast<__half2*>(&u1));
            float2 v2 = __half22float2(*reinterpret_cast<__half2*>(&u2));
            float2 v3 = __half22float2(*reinterpret_cast<__half2*>(&u3));
            acc.x += (v0.x + v1.x) + (v2.x + v3.x);
            acc.y += (v0.y + v1.y) + (v2.y + v3.y);
        }
        for (; k < chunk; ++k) {
            int j0 = __shfl_sync(0xffffffffu, cj, k);
            unsigned int u0 = Hin[(size_t)j0 * 32 + lane];
            float2 v0 = __half22float2(*reinterpret_cast<__half2*>(&u0));
            acc.x += v0.x; acc.y += v0.y;
        }
    }

    float2 o;
    o.x = (1.0f - ALPHA) * y.x + aid * (LAM * acc.x + z0.x);
    o.y = (1.0f - ALPHA) * y.y + aid * (LAM * acc.y + z0.y);

    if (!writeOut) {
        Yout[(size_t)w * 32 + lane] = o;
        __half2 hh = __float22half2_rn(o);
        Hout[(size_t)w * 32 + lane] = *reinterpret_cast<unsigned int*>(&hh);
    } else {
        if (lane < OUT_SZ / 2) {  // 20 float2 = 40 floats
            float2 bb = bout2[lane];
            outZ[(size_t)w * (OUT_SZ / 2) + lane] =
                make_float2(o.x + bb.x, o.y + bb.y);
        }
    }
}

// ---------------- launch ----------------
extern "C" void kernel_launch(void* const* d_in, const int* in_sizes, int n_in,
                              void* d_out, int out_size) {
    const float* X    = (const float*)d_in[0];
    const int*   row  = (const int*)d_in[1];
    const int*   col  = (const int*)d_in[2];
    const float* W1   = (const float*)d_in[3];
    const float* b1   = (const float*)d_in[4];
    const float* W2   = (const float*)d_in[5];
    const float* b2   = (const float*)d_in[6];
    const float* Wout = (const float*)d_in[7];
    const float* bout = (const float*)d_in[8];
    float*       out  = (float*)d_out;

    __half *pW1h, *pW2h, *pWoutPh, *pH1h, *pY0h, *pZha, *pZhb;
    float  *pZ0, *pZfa, *pZfb;
    cudaGetSymbolAddress((void**)&pW1h,   g_W1h);
    cudaGetSymbolAddress((void**)&pW2h,   g_W2h);
    cudaGetSymbolAddress((void**)&pWoutPh, g_WoutPh);
    cudaGetSymbolAddress((void**)&pH1h,   g_H1h);
    cudaGetSymbolAddress((void**)&pY0h,   g_Y0h);
    cudaGetSymbolAddress((void**)&pZ0,    g_Z0);
    cudaGetSymbolAddress((void**)&pZfa,   g_Zfa);
    cudaGetSymbolAddress((void**)&pZfb,   g_Zfb);
    cudaGetSymbolAddress((void**)&pZha,   g_Zha);
    cudaGetSymbolAddress((void**)&pZhb,   g_Zhb);

    // CSR build
    zero_deg_kernel<<<(N_NODES + 255) / 256, 256>>>();
    count_edges_kernel<<<1024, 256>>>(row);
    scan_block_kernel<<<SCAN_BLOCKS, 1024>>>();
    scan_sums_kernel<<<1, 64>>>();
    scan_apply_kernel<<<SCAN_BLOCKS, 1024>>>();
    scatter_edges_kernel<<<1024, 256>>>(row, col);

    // weight conversions (one kernel)
    {
        int tot = W1_U2 + W2_U2 + WOUTP;
        conv_weights_kernel<<<(tot + 255) / 256, 256>>>(W1, W2, Wout);
    }

    // MLP + projection on tensor cores
    dim3 g1((N_NODES + 63) / 64, HID / 64);
    wmma_gemm_kernel<0, true><<<g1, 128>>>(X, pW1h, b1, nullptr, nullptr, pH1h,
                                           N_NODES, IN_SZ, HID);
    wmma_gemm_kernel<1, false><<<g1, 128>>>(pH1h, pW2h, b2, nullptr, nullptr, pY0h,
                                            N_NODES, HID, HID);
    dim3 g2((N_NODES + 63) / 64, 1);
    wmma_gemm_kernel<2, false><<<g2, 128>>>(pY0h, pWoutPh, nullptr, pZ0, pZfa, pZha,
                                            N_NODES, HID, ZW);

    // 16 propagation steps on Z (width 64), ping-pong; last writes out+bout
    const int spmm_blocks = (N_NODES * 32 + 255) / 256;
    const float*  yin = pZfa;
    const __half* hin = pZha;
    for (int k = 0; k < NUM_STEPS; ++k) {
        int final = (k == NUM_STEPS - 1);
        float*  yout = (k & 1) ? pZfa : pZfb;
        __half* hout = (k & 1) ? pZha : pZhb;
        spmm_z_kernel<<<spmm_blocks, 256>>>(
            reinterpret_cast<const float2*>(yin),
            reinterpret_cast<const unsigned int*>(hin),
            reinterpret_cast<float2*>(yout),
            reinterpret_cast<unsigned int*>(hout),
            reinterpret_cast<const float2*>(pZ0),
            reinterpret_cast<float2*>(out),
            reinterpret_cast<const float2*>(bout),
            final);
        yin = yout;
        hin = hout;
    }
}

// round 10
// speedup vs baseline: 1.7157x; 1.0045x over previous
#include <cuda_runtime.h>
#include <cuda_fp16.h>
#include <cuda_bf16.h>
#include <mma.h>
#include <cstdint>

using namespace nvcuda;

#define N_NODES 50000
#define E_EDGES 800000
#define IN_SZ   256
#define HID     128
#define OUT_SZ  40
#define ZW      64        // padded propagation width (40 real + 24 zeros)
#define NUM_STEPS 16
#define LAM   1.0f
#define ALPHA 0.5f
#define SCAN_BLOCKS ((N_NODES + 1023) / 1024)

// ---------------- scratch (static device globals; no allocation) ----------------
__device__ __half g_W1h[IN_SZ * HID];
__device__ __half g_W2h[HID * HID];
__device__ __half g_WoutPh[HID * ZW];        // Wout zero-padded to 64 cols
__device__ __half g_H1h[N_NODES * HID];      // relu(X@W1+b1) fp16
__device__ __half g_Y0h[N_NODES * HID];      // MLP output fp16
__device__ float  g_Z0[N_NODES * ZW];        // anchor Z0 = Y0 @ WoutP (fp32)
__device__ float  g_Zfa[N_NODES * ZW];       // fp32 state ping
__device__ float  g_Zfb[N_NODES * ZW];       // fp32 state pong
__device__ __half g_Zha[N_NODES * ZW];       // fp16 gather mirror ping
__device__ __half g_Zhb[N_NODES * ZW];       // fp16 gather mirror pong
__device__ int    g_deg[N_NODES];
__device__ int    g_rowptr[N_NODES + 1];
__device__ int    g_fill[N_NODES];
__device__ int    g_csrcol[E_EDGES];
__device__ float  g_invd[N_NODES];
__device__ int    g_bsum[SCAN_BLOCKS];
__device__ int    g_boff[SCAN_BLOCKS];

// ---------------- CSR build ----------------
__global__ void zero_deg_kernel() {
    int i = blockIdx.x * blockDim.x + threadIdx.x;
    if (i < N_NODES) g_deg[i] = 0;
}

__global__ void count_edges_kernel(const int* __restrict__ row) {
    for (int e = blockIdx.x * blockDim.x + threadIdx.x; e < E_EDGES;
         e += gridDim.x * blockDim.x) {
        atomicAdd(&g_deg[row[e]], 1);
    }
}

// phase 1: per-block exclusive scan of deg -> rowptr (in-block), block sums
__global__ void scan_block_kernel() {
    __shared__ int wsum[32];
    int tid = threadIdx.x;
    int lane = tid & 31;
    int wid = tid >> 5;
    int i = blockIdx.x * 1024 + tid;
    int v = (i < N_NODES) ? g_deg[i] : 0;
    int x = v;
    #pragma unroll
    for (int off = 1; off < 32; off <<= 1) {
        int t = __shfl_up_sync(0xffffffffu, x, off);
        if (lane >= off) x += t;
    }
    if (lane == 31) wsum[wid] = x;
    __syncthreads();
    if (wid == 0) {
        int s = wsum[lane];
        #pragma unroll
        for (int off = 1; off < 32; off <<= 1) {
            int t = __shfl_up_sync(0xffffffffu, s, off);
            if (lane >= off) s += t;
        }
        wsum[lane] = s;
    }
    __syncthreads();
    int woff = (wid == 0) ? 0 : wsum[wid - 1];
    if (i < N_NODES) g_rowptr[i] = woff + x - v;   // in-block exclusive
    if (tid == 0) g_bsum[blockIdx.x] = wsum[31];
}

// phase 2: scan block sums (single small block)
__global__ void scan_sums_kernel() {
    __shared__ int s[64];
    int t = threadIdx.x;
    s[t] = (t < SCAN_BLOCKS) ? g_bsum[t] : 0;
    __syncthreads();
    #pragma unroll
    for (int off = 1; off < 64; off <<= 1) {
        int v = (t >= off) ? s[t - off] : 0;
        __syncthreads();
        s[t] += v;
        __syncthreads();
    }
    if (t < SCAN_BLOCKS) g_boff[t] = s[t] - g_bsum[t];  // exclusive
    if (t == 0) g_rowptr[N_NODES] = E_EDGES;
}

// phase 3: apply block offsets, init fill + invd
__global__ void scan_apply_kernel() {
    int i = blockIdx.x * 1024 + threadIdx.x;
    if (i >= N_NODES) return;
    int rp = g_rowptr[i] + g_boff[blockIdx.x];
    g_rowptr[i] = rp;
    g_fill[i]   = rp;
    g_invd[i]   = 1.0f / (LAM * (float)g_deg[i] + 1.0f);
}

__global__ void scatter_edges_kernel(const int* __restrict__ row,
                                     const int* __restrict__ col) {
    for (int e = blockIdx.x * blockDim.x + threadIdx.x; e < E_EDGES;
         e += gridDim.x * blockDim.x) {
        int r = row[e];
        int p = atomicAdd(&g_fill[r], 1);
        g_csrcol[p] = col[e];
    }
}

// ---------------- small weight conversions (one kernel) ----------------
#define W1_U2 (IN_SZ * HID / 4)     // 8192
#define W2_U2 (HID * HID / 4)       // 4096
#define WOUTP (HID * ZW)            // 8192
__global__ void conv_weights_kernel(const float* __restrict__ W1,
                                    const float* __restrict__ W2,
                                    const float* __restrict__ Wout) {
    int i = blockIdx.x * blockDim.x + threadIdx.x;
    if (i < W1_U2) {
        float4 v = reinterpret_cast<const float4*>(W1)[i];
        __half2 a = __float22half2_rn(make_float2(v.x, v.y));
        __half2 b = __float22half2_rn(make_float2(v.z, v.w));
        uint2 u;
        u.x = *reinterpret_cast<unsigned int*>(&a);
        u.y = *reinterpret_cast<unsigned int*>(&b);
        reinterpret_cast<uint2*>(g_W1h)[i] = u;
    } else if (i < W1_U2 + W2_U2) {
        int j = i - W1_U2;
        float4 v = reinterpret_cast<const float4*>(W2)[j];
        __half2 a = __float22half2_rn(make_float2(v.x, v.y));
        __half2 b = __float22half2_rn(make_float2(v.z, v.w));
        uint2 u;
        u.x = *reinterpret_cast<unsigned int*>(&a);
        u.y = *reinterpret_cast<unsigned int*>(&b);
        reinterpret_cast<uint2*>(g_W2h)[j] = u;
    } else if (i < W1_U2 + W2_U2 + WOUTP) {
        int j = i - W1_U2 - W2_U2;
        int r = j / ZW;
        int c = j % ZW;
        g_WoutPh[j] = (c < OUT_SZ) ? __float2half_rn(Wout[r * OUT_SZ + c])
                                   : __half(0.f);
    }
}

// ---------------- fp16 tensor-core GEMM (wmma), fp32 accum ----------------
// MODE 0: relu, write half out Ch                 (GEMM1: X@W1 -> H1h)
// MODE 1: write half out Ch                       (GEMM2: H1h@W2 -> Y0h)
// MODE 2: no bias; write fp32 C (anchor) + fp32 C2 (state) + half Ch (mirror)
// AF32:   A source is fp32 (converted during tile load)
template <int MODE, bool AF32>
__global__ void __launch_bounds__(128)
wmma_gemm_kernel(const void* __restrict__ Araw,
                 const __half* __restrict__ B,
                 const float* __restrict__ bias,
                 float* __restrict__ C,
                 float* __restrict__ C2,
                 __half* __restrict__ Ch,
                 int M, int K, int Nc) {
    const int BM = 64, BN = 64, BK = 32;
    __shared__ __align__(16) __half As[BM][BK + 16];
    __shared__ __align__(16) __half Bs[BK][BN + 8];
    __shared__ __align__(16) float  Cs[BM][BN];

    int tid = threadIdx.x;
    int wid = tid >> 5;
    int wr = wid >> 1;
    int wc = wid & 1;
    int bm = blockIdx.x * BM;
    int bn = blockIdx.y * BN;

    wmma::fragment<wmma::accumulator, 16, 16, 16, float> cf[2][2];
    #pragma unroll
    for (int i = 0; i < 2; ++i)
        #pragma unroll
        for (int j = 0; j < 2; ++j)
            wmma::fill_fragment(cf[i][j], 0.0f);

    for (int k0 = 0; k0 < K; k0 += BK) {
        if (AF32) {
            const float* A = (const float*)Araw;
            #pragma unroll
            for (int l = 0; l < 4; ++l) {
                int c  = tid + l * 128;
                int r  = c >> 3;
                int c4 = (c & 7) * 4;
                int gr = bm + r;
                float4 v = make_float4(0.f, 0.f, 0.f, 0.f);
                if (gr < M)
                    v = *reinterpret_cast<const float4*>(&A[(size_t)gr * K + k0 + c4]);
                __half2 h0 = __float22half2_rn(make_float2(v.x, v.y));
                __half2 h1 = __float22half2_rn(make_float2(v.z, v.w));
                *reinterpret_cast<__half2*>(&As[r][c4 + 0]) = h0;
                *reinterpret_cast<__half2*>(&As[r][c4 + 2]) = h1;
            }
        } else {
            const __half* A = (const __half*)Araw;
            #pragma unroll
            for (int l = 0; l < 2; ++l) {
                int c  = tid + l * 128;
                int r  = c >> 2;
                int cc = (c & 3) * 8;
                int gr = bm + r;
                uint4 v = make_uint4(0, 0, 0, 0);
                if (gr < M)
                    v = *reinterpret_cast<const uint4*>(&A[(size_t)gr * K + k0 + cc]);
                *reinterpret_cast<uint4*>(&As[r][cc]) = v;
            }
        }
        // B tile: 32 x 64 halves = 256 uint4
        #pragma unroll
        for (int l = 0; l < 2; ++l) {
            int c  = tid + l * 128;
            int r  = c >> 3;
            int cc = (c & 7) * 8;
            uint4 v = *reinterpret_cast<const uint4*>(&B[(size_t)(k0 + r) * Nc + bn + cc]);
            *reinterpret_cast<uint4*>(&Bs[r][cc]) = v;
        }
        __syncthreads();

        #pragma unroll
        for (int kk = 0; kk < 2; ++kk) {
            wmma::fragment<wmma::matrix_a, 16, 16, 16, __half, wmma::row_major> af[2];
            wmma::fragment<wmma::matrix_b, 16, 16, 16, __half, wmma::row_major> bf[2];
            #pragma unroll
            for (int i = 0; i < 2; ++i)
                wmma::load_matrix_sync(af[i], &As[wr * 32 + i * 16][kk * 16], BK + 16);
            #pragma unroll
            for (int j = 0; j < 2; ++j)
                wmma::load_matrix_sync(bf[j], &Bs[kk * 16][wc * 32 + j * 16], BN + 8);
            #pragma unroll
            for (int i = 0; i < 2; ++i)
                #pragma unroll
                for (int j = 0; j < 2; ++j)
                    wmma::mma_sync(cf[i][j], af[i], bf[j], cf[i][j]);
        }
        __syncthreads();
    }

    #pragma unroll
    for (int i = 0; i < 2; ++i)
        #pragma unroll
        for (int j = 0; j < 2; ++j)
            wmma::store_matrix_sync(&Cs[wr * 32 + i * 16][wc * 32 + j * 16],
                                    cf[i][j], BN, wmma::mem_row_major);
    __syncthreads();

    #pragma unroll 8
    for (int l = 0; l < 32; ++l) {
        int idx = tid + l * 128;
        int r  = idx >> 6;
        int cc = idx & 63;
        int gr = bm + r;
        if (gr >= M) continue;
        int gc = bn + cc;
        if (MODE == 2) {
            float v = Cs[r][cc];
            C[(size_t)gr * Nc + gc]  = v;
            C2[(size_t)gr * Nc + gc] = v;
            Ch[(size_t)gr * Nc + gc] = __float2half_rn(v);
        } else {
            float v = Cs[r][cc] + bias[gc];
            if (MODE == 0) v = fmaxf(v, 0.f);
            Ch[(size_t)gr * Nc + gc] = __float2half_rn(v);
        }
    }
}

// ---------------- fused SpMM + TWIRLS update on Z (width 64) ----------------
// One warp per row. Lane owns 2 features (float2 / half2).
// Gather = one LDG.32 per warp per edge: 32 lanes x 4B = 128B = 1 cacheline.
__global__ void __launch_bounds__(256)
spmm_z_kernel(const float2* __restrict__ Yin,
              const unsigned int* __restrict__ Hin,
              float2* __restrict__ Yout,
              unsigned int* __restrict__ Hout,
              const float2* __restrict__ Z0,
              float2* __restrict__ outZ,      // [N,20] float2 when final
              const float2* __restrict__ bout2,
              int writeOut) {
    int w    = (blockIdx.x * blockDim.x + threadIdx.x) >> 5;
    int lane = threadIdx.x & 31;
    if (w >= N_NODES) return;

    int s = g_rowptr[w];
    int e = g_rowptr[w + 1];

    float2 y  = Yin[(size_t)w * 32 + lane];
    float2 z0 = Z0[(size_t)w * 32 + lane];
    float aid = ALPHA * g_invd[w];

    float2 acc = make_float2(0.f, 0.f);
    for (int base = s; base < e; base += 32) {
        int chunk = min(32, e - base);
        int cj = g_csrcol[base + ((chunk == 32) ? lane : min(lane, chunk - 1))];

        int k = 0;
        int c8 = chunk & ~7;
        for (; k < c8; k += 8) {
            int j0 = __shfl_sync(0xffffffffu, cj, k + 0);
            int j1 = __shfl_sync(0xffffffffu, cj, k + 1);
            int j2 = __shfl_sync(0xffffffffu, cj, k + 2);
            int j3 = __shfl_sync(0xffffffffu, cj, k + 3);
            int j4 = __shfl_sync(0xffffffffu, cj, k + 4);
            int j5 = __shfl_sync(0xffffffffu, cj, k + 5);
            int j6 = __shfl_sync(0xffffffffu, cj, k + 6);
            int j7 = __shfl_sync(0xffffffffu, cj, k + 7);
            unsigned int u0 = Hin[(size_t)j0 * 32 + lane];
            unsigned int u1 = Hin[(size_t)j1 * 32 + lane];
            unsigned int u2 = Hin[(size_t)j2 * 32 + lane];
            unsigned int u3 = Hin[(size_t)j3 * 32 + lane];
            unsigned int u4 = Hin[(size_t)j4 * 32 + lane];
            unsigned int u5 = Hin[(size_t)j5 * 32 + lane];
            unsigned int u6 = Hin[(size_t)j6 * 32 + lane];
            unsigned int u7 = Hin[(size_t)j7 * 32 + lane];
            float2 v0 = __half22float2(*reinterpret_cast<__half2*>(&u0));
            float2 v1 = __half22float2(*reinterpret_cast<__half2*>(&u1));
            float2 v2 = __half22float2(*reinterpret_cast<__half2*>(&u2));
            float2 v3 = __half22float2(*reinterpret_cast<__half2*>(&u3));
            float2 v4 = __half22float2(*reinterpret_cast<__half2*>(&u4));
            float2 v5 = __half22float2(*reinterpret_cast<__half2*>(&u5));
            float2 v6 = __half22float2(*reinterpret_cast<__half2*>(&u6));
            float2 v7 = __half22float2(*reinterpret_cast<__half2*>(&u7));
            acc.x += ((v0.x + v1.x) + (v2.x + v3.x)) + ((v4.x + v5.x) + (v6.x + v7.x));
            acc.y += ((v0.y + v1.y) + (v2.y + v3.y)) + ((v4.y + v5.y) + (v6.y + v7.y));
        }
        int c4 = chunk & ~3;
        for (; k < c4; k += 4) {
            int j0 = __shfl_sync(0xffffffffu, cj, k + 0);
            int j1 = __shfl_sync(0xffffffffu, cj, k + 1);
            int j2 = __shfl_sync(0xffffffffu, cj, k + 2);
            int j3 = __shfl_sync(0xffffffffu, cj, k + 3);
            unsigned int u0 = Hin[(size_t)j0 * 32 + lane];
            unsigned int u1 = Hin[(size_t)j1 * 32 + lane];
            unsigned int u2 = Hin[(size_t)j2 * 32 + lane];
            unsigned int u3 = Hin[(size_t)j3 * 32 + lane];
            float2 v0 = __half22float2(*reinterpret_cast<__half2*>(&u0));
            float2 v1 = __half22float2(*reinterpret_cast<__half2*>(&u1));
            float2 v2 = __half22float2(*reinterpret_cast<__half2*>(&u2));
            float2 v3 = __half22float2(*reinterpret_cast<__half2*>(&u3));
            acc.x += (v0.x + v1.x) + (v2.x + v3.x);
            acc.y += (v0.y + v1.y) + (v2.y + v3.y);
        }
        for (; k < chunk; ++k) {
            int j0 = __shfl_sync(0xffffffffu, cj, k);
            unsigned int u0 = Hin[(size_t)j0 * 32 + lane];
            float2 v0 = __half22float2(*reinterpret_cast<__half2*>(&u0));
            acc.x += v0.x; acc.y += v0.y;
        }
    }

    float2 o;
    o.x = (1.0f - ALPHA) * y.x + aid * (LAM * acc.x + z0.x);
    o.y = (1.0f - ALPHA) * y.y + aid * (LAM * acc.y + z0.y);

    if (!writeOut) {
        Yout[(size_t)w * 32 + lane] = o;
        __half2 hh = __float22half2_rn(o);
        Hout[(size_t)w * 32 + lane] = *reinterpret_cast<unsigned int*>(&hh);
    } else {
        if (lane < OUT_SZ / 2) {  // 20 float2 = 40 floats
            float2 bb = bout2[lane];
            outZ[(size_t)w * (OUT_SZ / 2) + lane] =
                make_float2(o.x + bb.x, o.y + bb.y);
        }
    }
}

// ---------------- launch ----------------
extern "C" void kernel_launch(void* const* d_in, const int* in_sizes, int n_in,
                              void* d_out, int out_size) {
    const float* X    = (const float*)d_in[0];
    const int*   row  = (const int*)d_in[1];
    const int*   col  = (const int*)d_in[2];
    const float* W1   = (const float*)d_in[3];
    const float* b1   = (const float*)d_in[4];
    const float* W2   = (const float*)d_in[5];
    const float* b2   = (const float*)d_in[6];
    const float* Wout = (const float*)d_in[7];
    const float* bout = (const float*)d_in[8];
    float*       out  = (float*)d_out;

    __half *pW1h, *pW2h, *pWoutPh, *pH1h, *pY0h, *pZha, *pZhb;
    float  *pZ0, *pZfa, *pZfb;
    cudaGetSymbolAddress((void**)&pW1h,   g_W1h);
    cudaGetSymbolAddress((void**)&pW2h,   g_W2h);
    cudaGetSymbolAddress((void**)&pWoutPh, g_WoutPh);
    cudaGetSymbolAddress((void**)&pH1h,   g_H1h);
    cudaGetSymbolAddress((void**)&pY0h,   g_Y0h);
    cudaGetSymbolAddress((void**)&pZ0,    g_Z0);
    cudaGetSymbolAddress((void**)&pZfa,   g_Zfa);
    cudaGetSymbolAddress((void**)&pZfb,   g_Zfb);
    cudaGetSymbolAddress((void**)&pZha,   g_Zha);
    cudaGetSymbolAddress((void**)&pZhb,   g_Zhb);

    // CSR build
    zero_deg_kernel<<<(N_NODES + 255) / 256, 256>>>();
    count_edges_kernel<<<1024, 256>>>(row);
    scan_block_kernel<<<SCAN_BLOCKS, 1024>>>();
    scan_sums_kernel<<<1, 64>>>();
    scan_apply_kernel<<<SCAN_BLOCKS, 1024>>>();
    scatter_edges_kernel<<<1024, 256>>>(row, col);

    // weight conversions (one kernel)
    {
        int tot = W1_U2 + W2_U2 + WOUTP;
        conv_weights_kernel<<<(tot + 255) / 256, 256>>>(W1, W2, Wout);
    }

    // MLP + projection on tensor cores
    dim3 g1((N_NODES + 63) / 64, HID / 64);
    wmma_gemm_kernel<0, true><<<g1, 128>>>(X, pW1h, b1, nullptr, nullptr, pH1h,
                                           N_NODES, IN_SZ, HID);
    wmma_gemm_kernel<1, false><<<g1, 128>>>(pH1h, pW2h, b2, nullptr, nullptr, pY0h,
                                            N_NODES, HID, HID);
    dim3 g2((N_NODES + 63) / 64, 1);
    wmma_gemm_kernel<2, false><<<g2, 128>>>(pY0h, pWoutPh, nullptr, pZ0, pZfa, pZha,
                                            N_NODES, HID, ZW);

    // 16 propagation steps on Z (width 64), ping-pong; last writes out+bout
    const int spmm_blocks = (N_NODES * 32 + 255) / 256;
    const float*  yin = pZfa;
    const __half* hin = pZha;
    for (int k = 0; k < NUM_STEPS; ++k) {
        int final = (k == NUM_STEPS - 1);
        float*  yout = (k & 1) ? pZfa : pZfb;
        __half* hout = (k & 1) ? pZha : pZhb;
        spmm_z_kernel<<<spmm_blocks, 256>>>(
            reinterpret_cast<const float2*>(yin),
            reinterpret_cast<const unsigned int*>(hin),
            reinterpret_cast<float2*>(yout),
            reinterpret_cast<unsigned int*>(hout),
            reinterpret_cast<const float2*>(pZ0),
            reinterpret_cast<float2*>(out),
            reinterpret_cast<const float2*>(bout),
            final);
        yin = yout;
        hin = hout;
    }
}